// round 2
// baseline (speedup 1.0000x reference)
#include <cuda_runtime.h>
#include <cstdint>

#define BB 8
#define NN 2048
#define DD 128
#define ALPHA 0.2f
#define LOG2E 1.44269504f
#define NW (NN/32)   // adjacency words per row

// ---------------- device scratch (zero-initialized at load) ----------------
__device__ float    g_h  [BB*NN*DD];   // h = (x*m) @ W
__device__ float    g_hc [BB*NN*DD];   // h compacted over active j (zero-padded to 32)
__device__ float    g_el [BB*NN];
__device__ float    g_er [BB*NN];
__device__ float    g_erc[BB*NN];      // e_r compacted
__device__ int      g_act[BB*NN];      // active node list per batch
__device__ int      g_cnt[BB];         // active count per batch
__device__ unsigned g_adjc[(size_t)BB*NN*NW]; // packed allowed-bits, compacted i & j

// ---------------- K1: deterministic compaction (prefix scan) ----------------
__global__ void k1_compact(const int* __restrict__ nm) {
    int b = blockIdx.x;
    int t = threadIdx.x;
    __shared__ int part[256];
    const int* m = nm + b*NN;
    int base = t*8;
    int flags[8]; int c = 0;
#pragma unroll
    for (int k = 0; k < 8; k++) { flags[k] = (m[base+k] != 0); c += flags[k]; }
    part[t] = c;
    __syncthreads();
    for (int off = 1; off < 256; off <<= 1) {
        int add = (t >= off) ? part[t-off] : 0;
        __syncthreads();
        part[t] += add;
        __syncthreads();
    }
    int pos = part[t] - c;   // exclusive prefix
#pragma unroll
    for (int k = 0; k < 8; k++) if (flags[k]) { g_act[b*NN + pos] = base + k; pos++; }
    if (t == 255) g_cnt[b] = part[255];
}

// ---------------- K2: h = (x*m)@W, e_l, e_r; beta rows for masked i --------
__global__ __launch_bounds__(128) void k2_gemm(
    const float* __restrict__ x, const int* __restrict__ nm,
    const float* __restrict__ W, const float* __restrict__ a_l,
    const float* __restrict__ a_r, const float* __restrict__ beta,
    float* __restrict__ out)
{
    __shared__ float xs[32][DD];
    int tid = threadIdx.x;
    int tx = tid & 31, ty = tid >> 5;
    int r0 = blockIdx.x * 32;

#pragma unroll 4
    for (int i = 0; i < 32; i++) {
        int g = r0 + i;
        float mv = (nm[g] != 0) ? 1.f : 0.f;
        xs[i][tid] = x[(size_t)g*DD + tid] * mv;
    }
    __syncthreads();

    float4 acc[8];
#pragma unroll
    for (int r = 0; r < 8; r++) acc[r] = make_float4(0.f,0.f,0.f,0.f);

    const float4* W4 = reinterpret_cast<const float4*>(W);
#pragma unroll 4
    for (int k = 0; k < DD; k++) {
        float4 w4 = W4[k*32 + tx];
#pragma unroll
        for (int r = 0; r < 8; r++) {
            float xv = xs[ty*8 + r][k];
            acc[r].x += xv*w4.x; acc[r].y += xv*w4.y;
            acc[r].z += xv*w4.z; acc[r].w += xv*w4.w;
        }
    }

    float4 alv = *reinterpret_cast<const float4*>(a_l + tx*4);
    float4 arv = *reinterpret_cast<const float4*>(a_r + tx*4);
#pragma unroll
    for (int r = 0; r < 8; r++) {
        int g = r0 + ty*8 + r;
        *reinterpret_cast<float4*>(&g_h[(size_t)g*DD + tx*4]) = acc[r];
        float pl = acc[r].x*alv.x + acc[r].y*alv.y + acc[r].z*alv.z + acc[r].w*alv.w;
        float pr = acc[r].x*arv.x + acc[r].y*arv.y + acc[r].z*arv.z + acc[r].w*arv.w;
#pragma unroll
        for (int off = 16; off; off >>= 1) {
            pl += __shfl_down_sync(0xffffffffu, pl, off);
            pr += __shfl_down_sync(0xffffffffu, pr, off);
        }
        if (tx == 0) { g_el[g] = pl; g_er[g] = pr; }
    }

    // masked rows -> output is exactly beta (proof: out row==0 -> LN -> beta)
#pragma unroll 4
    for (int i = 0; i < 32; i++) {
        int g = r0 + i;
        if (nm[g] == 0) out[(size_t)g*DD + tid] = beta[tid];
    }
}

// ---------------- K3: compacted adjacency bitmask + hc + erc ----------------
__global__ void k3_adjc(const int* __restrict__ adj) {
    int b   = blockIdx.y;
    int ii  = blockIdx.x;
    int cnt = g_cnt[b];
    int pad = (cnt + 31) & ~31;
    int tid = threadIdx.x;

    if (ii >= cnt) {
        // zero-pad hc rows [cnt, pad) so K4 can run full 32-wide chunks
        if (ii < pad && tid < 32)
            *reinterpret_cast<float4*>(&g_hc[((size_t)b*NN + ii)*DD + tid*4]) =
                make_float4(0.f,0.f,0.f,0.f);
        return;
    }
    int i = g_act[b*NN + ii];
    if (tid < 32)
        *reinterpret_cast<float4*>(&g_hc[((size_t)b*NN + ii)*DD + tid*4]) =
        *reinterpret_cast<const float4*>(&g_h[((size_t)b*NN + i)*DD + tid*4]);
    if (ii == 0) {
        for (int jj = tid; jj < cnt; jj += 256)
            g_erc[b*NN + jj] = g_er[b*NN + g_act[b*NN + jj]];
    }

    const int* arow = adj + ((size_t)b*NN + i)*NN;
    int lane = tid & 31, wid = tid >> 5;
    unsigned* dst = g_adjc + ((size_t)b*NN + ii)*NW;
    for (int jj0 = wid*32; jj0 < pad; jj0 += 256) {
        int jj = jj0 + lane;
        int a = 0;
        if (jj < cnt) a = arow[g_act[b*NN + jj]];
        unsigned bits = __ballot_sync(0xffffffffu, a != 0);
        if (lane == 0) dst[jj0 >> 5] = bits;
    }
}

// ---------------- K4: fused score/softmax/AV/residual/LayerNorm -------------
#define ACC_ROW(r, pv) { acc[r].x += (pv)*h4.x; acc[r].y += (pv)*h4.y; \
                         acc[r].z += (pv)*h4.z; acc[r].w += (pv)*h4.w; }

__global__ __launch_bounds__(128) void k4_attn(
    const float* __restrict__ x, const float* __restrict__ gamma,
    const float* __restrict__ beta, float* __restrict__ out)
{
    __shared__ float p_s[4][32][8];
    int b    = blockIdx.y;
    int cnt  = g_cnt[b];
    int lane = threadIdx.x & 31, wid = threadIdx.x >> 5;
    int base_ii = blockIdx.x * 32 + wid * 8;
    if (base_ii >= cnt) return;

    float el[8]; int irow[8];
#pragma unroll
    for (int r = 0; r < 8; r++) {
        int ii = base_ii + r;
        int iw = (ii < cnt) ? ii : (cnt - 1);
        irow[r] = g_act[b*NN + iw];
        el[r]   = g_el[b*NN + irow[r]];
    }

    float4 acc[8];
    float  psum[8];
#pragma unroll
    for (int r = 0; r < 8; r++) { acc[r] = make_float4(0.f,0.f,0.f,0.f); psum[r] = 0.f; }

    int nch = (cnt + 31) >> 5;
    const float*    hcb  = g_hc  + (size_t)b*NN*DD + lane*4;
    const float*    ercb = g_erc + b*NN;
    const unsigned* adjr = g_adjc + ((size_t)b*NN + base_ii)*NW;

    for (int jc = 0; jc < nch; jc++) {
        float er = ercb[jc*32 + lane];
        float p[8];
#pragma unroll
        for (int r = 0; r < 8; r++) {
            unsigned w = adjr[(size_t)r*NW + jc];
            float s = el[r] + er;
            s = (s > 0.f) ? s : ALPHA*s;
            p[r] = ((w >> lane) & 1u) ? exp2f(s*LOG2E) : 0.f;
            psum[r] += p[r];
        }
        *reinterpret_cast<float4*>(&p_s[wid][lane][0]) = make_float4(p[0],p[1],p[2],p[3]);
        *reinterpret_cast<float4*>(&p_s[wid][lane][4]) = make_float4(p[4],p[5],p[6],p[7]);
        __syncwarp();
        const float* hp = hcb + (size_t)jc*32*DD;
#pragma unroll 4
        for (int l = 0; l < 32; l++) {
            float4 h4 = *reinterpret_cast<const float4*>(hp + (size_t)l*DD);
            float4 pa = *reinterpret_cast<const float4*>(&p_s[wid][l][0]);
            float4 pb = *reinterpret_cast<const float4*>(&p_s[wid][l][4]);
            ACC_ROW(0, pa.x) ACC_ROW(1, pa.y) ACC_ROW(2, pa.z) ACC_ROW(3, pa.w)
            ACC_ROW(4, pb.x) ACC_ROW(5, pb.y) ACC_ROW(6, pb.z) ACC_ROW(7, pb.w)
        }
        __syncwarp();
    }

    float tot[8];
#pragma unroll
    for (int r = 0; r < 8; r++) {
        float t = psum[r];
#pragma unroll
        for (int off = 16; off; off >>= 1) t += __shfl_xor_sync(0xffffffffu, t, off);
        tot[r] = t;
    }

    // Exact fallback: a row with zero allowed neighbors has uniform softmax(1/N)
    bool anyz = false;
#pragma unroll
    for (int r = 0; r < 8; r++) if (base_ii + r < cnt && tot[r] <= 0.f) anyz = true;
    if (__any_sync(0xffffffffu, anyz)) {
        for (int jc = 0; jc < nch; jc++) {
            const float* hp = hcb + (size_t)jc*32*DD;
            for (int l = 0; l < 32; l++) {
                float4 h4 = *reinterpret_cast<const float4*>(hp + (size_t)l*DD);
#pragma unroll
                for (int r = 0; r < 8; r++)
                    if (tot[r] <= 0.f) { acc[r].x += h4.x; acc[r].y += h4.y;
                                         acc[r].z += h4.z; acc[r].w += h4.w; }
            }
        }
    }

    float4 gv = *reinterpret_cast<const float4*>(gamma + lane*4);
    float4 bv = *reinterpret_cast<const float4*>(beta  + lane*4);
#pragma unroll
    for (int r = 0; r < 8; r++) {
        if (base_ii + r >= cnt) break;
        float inv = (tot[r] > 0.f) ? (1.f/tot[r]) : (1.f/(float)NN);
        int g = b*NN + irow[r];
        float4 x4 = *reinterpret_cast<const float4*>(x + (size_t)g*DD + lane*4);
        float4 v;
        v.x = acc[r].x*inv + x4.x;  v.y = acc[r].y*inv + x4.y;
        v.z = acc[r].z*inv + x4.z;  v.w = acc[r].w*inv + x4.w;
        float s1 = v.x + v.y + v.z + v.w;
        float s2 = v.x*v.x + v.y*v.y + v.z*v.z + v.w*v.w;
#pragma unroll
        for (int off = 16; off; off >>= 1) {
            s1 += __shfl_xor_sync(0xffffffffu, s1, off);
            s2 += __shfl_xor_sync(0xffffffffu, s2, off);
        }
        float mu  = s1 * (1.f/128.f);
        float var = s2 * (1.f/128.f) - mu*mu;
        float rs  = rsqrtf(var + 1e-5f);
        float4 o;
        o.x = (v.x - mu)*rs*gv.x + bv.x;
        o.y = (v.y - mu)*rs*gv.y + bv.y;
        o.z = (v.z - mu)*rs*gv.z + bv.z;
        o.w = (v.w - mu)*rs*gv.w + bv.w;
        *reinterpret_cast<float4*>(out + (size_t)g*DD + lane*4) = o;
    }
}

// ---------------- launcher ---------------------------------------------------
extern "C" void kernel_launch(void* const* d_in, const int* in_sizes, int n_in,
                              void* d_out, int out_size) {
    const float* x     = (const float*)d_in[0];
    const int*   adj   = (const int*)  d_in[1];
    const int*   nm    = (const int*)  d_in[2];
    const float* W     = (const float*)d_in[3];
    const float* a_l   = (const float*)d_in[4];
    const float* a_r   = (const float*)d_in[5];
    const float* gamma = (const float*)d_in[6];
    const float* beta  = (const float*)d_in[7];
    float* out = (float*)d_out;

    k1_compact<<<BB, 256>>>(nm);
    k2_gemm<<<(BB*NN)/32, 128>>>(x, nm, W, a_l, a_r, beta, out);
    k3_adjc<<<dim3(NN, BB), 256>>>(adj);
    k4_attn<<<dim3(NN/32, BB), 128>>>(x, gamma, beta, out);
}

// round 3
// speedup vs baseline: 1.3544x; 1.3544x over previous
#include <cuda_runtime.h>
#include <cstdint>

#define BB 8
#define NN 2048
#define DD 128
#define ALPHA 0.2f
#define LOG2E 1.44269504f
#define NW (NN/32)   // adjacency words per row
#define SPLIT 4

// ---------------- device scratch ----------------
__device__ float    g_h  [BB*NN*DD];            // h = (x*m) @ W
__device__ float    g_hc [BB*NN*DD];            // h compacted over active j (zero-padded)
__device__ float    g_el [BB*NN];
__device__ float    g_er [BB*NN];
__device__ float    g_erc[BB*NN];               // e_r compacted
__device__ int      g_act[BB*NN];               // active node list per batch
__device__ int      g_cnt[BB];                  // active count per batch
__device__ unsigned g_adjc[(size_t)BB*NN*NW];   // packed allowed-bits (compacted i & j)
__device__ float    g_pacc[(size_t)SPLIT*BB*NN*DD]; // split partial AV accumulators
__device__ float    g_psumP[SPLIT][BB*NN];      // split partial softmax sums

// f32x2 packed-FMA helpers (Blackwell dual-fp32)
__device__ __forceinline__ unsigned long long pack2(float p) {
    unsigned long long r;
    unsigned u = __float_as_uint(p);
    asm("mov.b64 %0, {%1, %1};" : "=l"(r) : "r"(u));
    return r;
}
__device__ __forceinline__ void fma2(unsigned long long& acc,
                                     unsigned long long a, unsigned long long b) {
    asm("fma.rn.f32x2 %0, %1, %2, %0;" : "+l"(acc) : "l"(a), "l"(b));
}

// ---------------- K1: deterministic compaction (prefix scan) ----------------
__global__ void k1_compact(const int* __restrict__ nm) {
    int b = blockIdx.x;
    int t = threadIdx.x;
    __shared__ int part[256];
    const int* m = nm + b*NN;
    int base = t*8;
    int flags[8]; int c = 0;
#pragma unroll
    for (int k = 0; k < 8; k++) { flags[k] = (m[base+k] != 0); c += flags[k]; }
    part[t] = c;
    __syncthreads();
    for (int off = 1; off < 256; off <<= 1) {
        int add = (t >= off) ? part[t-off] : 0;
        __syncthreads();
        part[t] += add;
        __syncthreads();
    }
    int pos = part[t] - c;
#pragma unroll
    for (int k = 0; k < 8; k++) if (flags[k]) { g_act[b*NN + pos] = base + k; pos++; }
    if (t == 255) g_cnt[b] = part[255];
}

// ---------------- K2: h = (x*m)@W, e_l, e_r; beta rows for masked i --------
__global__ __launch_bounds__(128) void k2_gemm(
    const float* __restrict__ x, const int* __restrict__ nm,
    const float* __restrict__ W, const float* __restrict__ a_l,
    const float* __restrict__ a_r, const float* __restrict__ beta,
    float* __restrict__ out)
{
    __shared__ float xs[32][DD];
    int tid = threadIdx.x;
    int tx = tid & 31, ty = tid >> 5;
    int r0 = blockIdx.x * 32;

#pragma unroll 4
    for (int i = 0; i < 32; i++) {
        int g = r0 + i;
        float mv = (nm[g] != 0) ? 1.f : 0.f;
        xs[i][tid] = x[(size_t)g*DD + tid] * mv;
    }
    __syncthreads();

    float4 acc[8];
#pragma unroll
    for (int r = 0; r < 8; r++) acc[r] = make_float4(0.f,0.f,0.f,0.f);

    const float4* W4 = reinterpret_cast<const float4*>(W);
#pragma unroll 4
    for (int k = 0; k < DD; k++) {
        float4 w4 = W4[k*32 + tx];
#pragma unroll
        for (int r = 0; r < 8; r++) {
            float xv = xs[ty*8 + r][k];
            acc[r].x += xv*w4.x; acc[r].y += xv*w4.y;
            acc[r].z += xv*w4.z; acc[r].w += xv*w4.w;
        }
    }

    float4 alv = *reinterpret_cast<const float4*>(a_l + tx*4);
    float4 arv = *reinterpret_cast<const float4*>(a_r + tx*4);
#pragma unroll
    for (int r = 0; r < 8; r++) {
        int g = r0 + ty*8 + r;
        *reinterpret_cast<float4*>(&g_h[(size_t)g*DD + tx*4]) = acc[r];
        float pl = acc[r].x*alv.x + acc[r].y*alv.y + acc[r].z*alv.z + acc[r].w*alv.w;
        float pr = acc[r].x*arv.x + acc[r].y*arv.y + acc[r].z*arv.z + acc[r].w*arv.w;
#pragma unroll
        for (int off = 16; off; off >>= 1) {
            pl += __shfl_down_sync(0xffffffffu, pl, off);
            pr += __shfl_down_sync(0xffffffffu, pr, off);
        }
        if (tx == 0) { g_el[g] = pl; g_er[g] = pr; }
    }

    // masked rows -> output is exactly beta (out row==0 -> LN -> beta)
#pragma unroll 4
    for (int i = 0; i < 32; i++) {
        int g = r0 + i;
        if (nm[g] == 0) out[(size_t)g*DD + tid] = beta[tid];
    }
}

// ---------------- K3: compacted adjacency bitmask + hc + erc ----------------
__global__ void k3_adjc(const int* __restrict__ adj) {
    int b   = blockIdx.y;
    int ii  = blockIdx.x;
    int cnt = g_cnt[b];
    int pad = (cnt + 31) & ~31;
    int tid = threadIdx.x;

    if (ii >= cnt) {
        if (ii < pad && tid < 32)
            *reinterpret_cast<float4*>(&g_hc[((size_t)b*NN + ii)*DD + tid*4]) =
                make_float4(0.f,0.f,0.f,0.f);
        return;
    }
    int i = g_act[b*NN + ii];
    if (tid < 32)
        *reinterpret_cast<float4*>(&g_hc[((size_t)b*NN + ii)*DD + tid*4]) =
        *reinterpret_cast<const float4*>(&g_h[((size_t)b*NN + i)*DD + tid*4]);
    if (ii == 0) {
        for (int jj = tid; jj < cnt; jj += 256)
            g_erc[b*NN + jj] = g_er[b*NN + g_act[b*NN + jj]];
    }

    const int* arow = adj + ((size_t)b*NN + i)*NN;
    int lane = tid & 31, wid = tid >> 5;
    unsigned* dst = g_adjc + ((size_t)b*NN + ii)*NW;
    for (int jj0 = wid*32; jj0 < pad; jj0 += 256) {
        int jj = jj0 + lane;
        int a = 0;
        if (jj < cnt) a = arow[g_act[b*NN + jj]];
        unsigned bits = __ballot_sync(0xffffffffu, a != 0);
        if (lane == 0) dst[jj0 >> 5] = bits;
    }
}

// ---------------- K4: split score/softmax-sum/AV partial ---------------------
__global__ __launch_bounds__(128) void k4_attn(void)
{
    __shared__ float p_s[4][32][8];
    int b    = blockIdx.z;
    int sid  = blockIdx.y;
    int cnt  = g_cnt[b];
    int lane = threadIdx.x & 31, wid = threadIdx.x >> 5;
    int base_ii = blockIdx.x * 32 + wid * 8;
    if (blockIdx.x * 32 >= cnt) return;

    int nch = (cnt + 31) >> 5;
    int cs  = (nch + SPLIT - 1) / SPLIT;
    int jc0 = sid * cs;
    int jc1 = min(nch, jc0 + cs);

    float el[8];
#pragma unroll
    for (int r = 0; r < 8; r++) {
        int ii = base_ii + r;
        int iw = (ii < cnt) ? ii : (cnt - 1);
        el[r] = g_el[b*NN + g_act[b*NN + iw]];
    }

    unsigned long long acc01[8], acc23[8];
    float psum[8];
#pragma unroll
    for (int r = 0; r < 8; r++) { acc01[r] = 0ull; acc23[r] = 0ull; psum[r] = 0.f; }

    const float*    hcb  = g_hc  + (size_t)b*NN*DD + lane*4;
    const float*    ercb = g_erc + b*NN;
    const unsigned* adjr = g_adjc + ((size_t)b*NN + base_ii)*NW;

    for (int jc = jc0; jc < jc1; jc++) {
        float er = ercb[jc*32 + lane];
        float p[8];
#pragma unroll
        for (int r = 0; r < 8; r++) {
            unsigned w = adjr[(size_t)r*NW + jc];
            float s = el[r] + er;
            s = (s > 0.f) ? s : ALPHA*s;
            p[r] = ((w >> lane) & 1u) ? exp2f(s*LOG2E) : 0.f;
            psum[r] += p[r];
        }
        *reinterpret_cast<float4*>(&p_s[wid][lane][0]) = make_float4(p[0],p[1],p[2],p[3]);
        *reinterpret_cast<float4*>(&p_s[wid][lane][4]) = make_float4(p[4],p[5],p[6],p[7]);
        __syncwarp();

        const ulonglong2* hp =
            reinterpret_cast<const ulonglong2*>(hcb + (size_t)jc*32*DD);
#pragma unroll 8
        for (int l = 0; l < 32; l++) {
            ulonglong2 h2 = hp[l*32];   // row stride = 128 floats = 32 ulonglong2
            float4 pa = *reinterpret_cast<const float4*>(&p_s[wid][l][0]);
            float4 pb = *reinterpret_cast<const float4*>(&p_s[wid][l][4]);
            unsigned long long pp;
            pp = pack2(pa.x); fma2(acc01[0], h2.x, pp); fma2(acc23[0], h2.y, pp);
            pp = pack2(pa.y); fma2(acc01[1], h2.x, pp); fma2(acc23[1], h2.y, pp);
            pp = pack2(pa.z); fma2(acc01[2], h2.x, pp); fma2(acc23[2], h2.y, pp);
            pp = pack2(pa.w); fma2(acc01[3], h2.x, pp); fma2(acc23[3], h2.y, pp);
            pp = pack2(pb.x); fma2(acc01[4], h2.x, pp); fma2(acc23[4], h2.y, pp);
            pp = pack2(pb.y); fma2(acc01[5], h2.x, pp); fma2(acc23[5], h2.y, pp);
            pp = pack2(pb.z); fma2(acc01[6], h2.x, pp); fma2(acc23[6], h2.y, pp);
            pp = pack2(pb.w); fma2(acc01[7], h2.x, pp); fma2(acc23[7], h2.y, pp);
        }
        __syncwarp();
    }

    // write partials
#pragma unroll
    for (int r = 0; r < 8; r++) {
        float t = psum[r];
#pragma unroll
        for (int off = 16; off; off >>= 1) t += __shfl_xor_sync(0xffffffffu, t, off);
        int ii = base_ii + r;
        if (lane == 0 && ii < NN) g_psumP[sid][b*NN + ii] = t;
        ulonglong2* dst = reinterpret_cast<ulonglong2*>(
            g_pacc + (size_t)sid*BB*NN*DD + ((size_t)b*NN + ii)*DD);
        dst[lane] = make_ulonglong2(acc01[r], acc23[r]);
    }
}

// ---------------- K5: reduce splits + normalize + residual + LayerNorm ------
__global__ __launch_bounds__(128) void k5_finish(
    const float* __restrict__ x, const float* __restrict__ gamma,
    const float* __restrict__ beta, float* __restrict__ out)
{
    int b    = blockIdx.y;
    int cnt  = g_cnt[b];
    int lane = threadIdx.x & 31, wid = threadIdx.x >> 5;
    int base_ii = blockIdx.x * 32 + wid * 8;
    if (base_ii >= cnt) return;

    float4 gv = *reinterpret_cast<const float4*>(gamma + lane*4);
    float4 bv = *reinterpret_cast<const float4*>(beta  + lane*4);

#pragma unroll
    for (int r = 0; r < 8; r++) {
        int ii = base_ii + r;
        if (ii >= cnt) break;
        int g = b*NN + g_act[b*NN + ii];

        float4 a = make_float4(0.f,0.f,0.f,0.f);
        float tot = 0.f;
#pragma unroll
        for (int s = 0; s < SPLIT; s++) {
            const float4* pp = reinterpret_cast<const float4*>(
                g_pacc + (size_t)s*BB*NN*DD + ((size_t)b*NN + ii)*DD);
            float4 t = pp[lane];
            a.x += t.x; a.y += t.y; a.z += t.z; a.w += t.w;
            tot += g_psumP[s][b*NN + ii];
        }

        float inv;
        if (tot > 0.f) {
            inv = 1.f / tot;
        } else {
            // exact fallback: uniform softmax over all N (masked h rows are 0)
            a = make_float4(0.f,0.f,0.f,0.f);
            const float* hcb = g_hc + (size_t)b*NN*DD + lane*4;
            for (int jj = 0; jj < cnt; jj++) {
                float4 h4 = *reinterpret_cast<const float4*>(hcb + (size_t)jj*DD);
                a.x += h4.x; a.y += h4.y; a.z += h4.z; a.w += h4.w;
            }
            inv = 1.f / (float)NN;
        }

        float4 x4 = *reinterpret_cast<const float4*>(x + (size_t)g*DD + lane*4);
        float4 v;
        v.x = a.x*inv + x4.x;  v.y = a.y*inv + x4.y;
        v.z = a.z*inv + x4.z;  v.w = a.w*inv + x4.w;
        float s1 = v.x + v.y + v.z + v.w;
        float s2 = v.x*v.x + v.y*v.y + v.z*v.z + v.w*v.w;
#pragma unroll
        for (int off = 16; off; off >>= 1) {
            s1 += __shfl_xor_sync(0xffffffffu, s1, off);
            s2 += __shfl_xor_sync(0xffffffffu, s2, off);
        }
        float mu  = s1 * (1.f/128.f);
        float var = s2 * (1.f/128.f) - mu*mu;
        float rs  = rsqrtf(var + 1e-5f);
        float4 o;
        o.x = (v.x - mu)*rs*gv.x + bv.x;
        o.y = (v.y - mu)*rs*gv.y + bv.y;
        o.z = (v.z - mu)*rs*gv.z + bv.z;
        o.w = (v.w - mu)*rs*gv.w + bv.w;
        *reinterpret_cast<float4*>(out + (size_t)g*DD + lane*4) = o;
    }
}

// ---------------- launcher ---------------------------------------------------
extern "C" void kernel_launch(void* const* d_in, const int* in_sizes, int n_in,
                              void* d_out, int out_size) {
    const float* x     = (const float*)d_in[0];
    const int*   adj   = (const int*)  d_in[1];
    const int*   nm    = (const int*)  d_in[2];
    const float* W     = (const float*)d_in[3];
    const float* a_l   = (const float*)d_in[4];
    const float* a_r   = (const float*)d_in[5];
    const float* gamma = (const float*)d_in[6];
    const float* beta  = (const float*)d_in[7];
    float* out = (float*)d_out;

    k1_compact<<<BB, 256>>>(nm);
    k2_gemm<<<(BB*NN)/32, 128>>>(x, nm, W, a_l, a_r, beta, out);
    k3_adjc<<<dim3(NN, BB), 256>>>(adj);
    k4_attn<<<dim3(NN/32, SPLIT, BB), 128>>>();
    k5_finish<<<dim3(NN/32, BB), 128>>>(x, gamma, beta, out);
}

// round 4
// speedup vs baseline: 1.5002x; 1.1076x over previous
#include <cuda_runtime.h>
#include <cstdint>

#define BB 8
#define NN 2048
#define DD 128
#define ALPHA 0.2f
#define LOG2E 1.44269504f
#define NW (NN/32)
#define SPLIT 4

// ---------------- device scratch ----------------
__device__ float    g_h  [BB*NN*DD];
__device__ float    g_hc [BB*NN*DD];            // compacted h (zero-padded to 32)
__device__ float    g_el [BB*NN];
__device__ float    g_er [BB*NN];
__device__ float    g_erc[BB*NN];
__device__ int      g_act[BB*NN];
__device__ int      g_cnt[BB];
__device__ unsigned g_adjc[(size_t)BB*NN*NW];
__device__ float    g_pacc[(size_t)SPLIT*BB*NN*DD];
__device__ float    g_psumP[SPLIT][BB*NN];

// ---- packed f32x2 helpers ----
__device__ __forceinline__ unsigned long long pack2(float p) {
    unsigned long long r; unsigned u = __float_as_uint(p);
    asm("mov.b64 %0, {%1, %1};" : "=l"(r) : "r"(u)); return r;
}
__device__ __forceinline__ unsigned long long pk2(float a, float b) {
    unsigned long long r;
    asm("mov.b64 %0, {%1, %2};" : "=l"(r) : "f"(a), "f"(b)); return r;
}
__device__ __forceinline__ void fma2(unsigned long long& acc,
                                     unsigned long long a, unsigned long long b) {
    asm("fma.rn.f32x2 %0, %1, %2, %0;" : "+l"(acc) : "l"(a), "l"(b));
}
__device__ __forceinline__ void unpk2(unsigned long long v, float& a, float& b) {
    asm("mov.b64 {%0, %1}, %2;" : "=f"(a), "=f"(b) : "l"(v));
}
// ---- tf32 mma helpers ----
__device__ __forceinline__ unsigned cvt_tf32(float f) {
    unsigned r; asm("cvt.rna.tf32.f32 %0, %1;" : "=r"(r) : "f"(f)); return r;
}
__device__ __forceinline__ void mma_tf32(float4& d, unsigned a0, unsigned a1,
                                         unsigned a2, unsigned a3,
                                         unsigned b0, unsigned b1) {
    asm("mma.sync.aligned.m16n8k8.row.col.f32.tf32.tf32.f32 "
        "{%0,%1,%2,%3}, {%4,%5,%6,%7}, {%8,%9}, {%0,%1,%2,%3};"
        : "+f"(d.x), "+f"(d.y), "+f"(d.z), "+f"(d.w)
        : "r"(a0), "r"(a1), "r"(a2), "r"(a3), "r"(b0), "r"(b1));
}

// ---------------- K1: deterministic compaction ----------------
__global__ void k1_compact(const int* __restrict__ nm) {
    int b = blockIdx.x, t = threadIdx.x;
    __shared__ int part[256];
    const int* m = nm + b*NN;
    int base = t*8, flags[8], c = 0;
#pragma unroll
    for (int k = 0; k < 8; k++) { flags[k] = (m[base+k] != 0); c += flags[k]; }
    part[t] = c; __syncthreads();
    for (int off = 1; off < 256; off <<= 1) {
        int add = (t >= off) ? part[t-off] : 0;
        __syncthreads(); part[t] += add; __syncthreads();
    }
    int pos = part[t] - c;
#pragma unroll
    for (int k = 0; k < 8; k++) if (flags[k]) { g_act[b*NN + pos] = base + k; pos++; }
    if (t == 255) g_cnt[b] = part[255];
}

// ---------------- K2: h=(x*m)@W (f32x2), e_l/e_r, beta for masked rows ------
__global__ __launch_bounds__(128) void k2_gemm(
    const float* __restrict__ x, const int* __restrict__ nm,
    const float* __restrict__ W, const float* __restrict__ a_l,
    const float* __restrict__ a_r, const float* __restrict__ beta,
    float* __restrict__ out)
{
    __shared__ float xs[32][DD];
    int tid = threadIdx.x, tx = tid & 31, ty = tid >> 5;
    int r0 = blockIdx.x * 32;

#pragma unroll 4
    for (int i = 0; i < 32; i++) {
        int g = r0 + i;
        float mv = (nm[g] != 0) ? 1.f : 0.f;
        xs[i][tid] = x[(size_t)g*DD + tid] * mv;
    }
    __syncthreads();

    unsigned long long accxy[8], acczw[8];
#pragma unroll
    for (int r = 0; r < 8; r++) { accxy[r] = 0ull; acczw[r] = 0ull; }

    const float4* W4 = reinterpret_cast<const float4*>(W);
#pragma unroll 4
    for (int k = 0; k < DD; k++) {
        float4 w4 = W4[k*32 + tx];
        unsigned long long wxy = pk2(w4.x, w4.y), wzw = pk2(w4.z, w4.w);
#pragma unroll
        for (int r = 0; r < 8; r++) {
            unsigned long long xv = pack2(xs[ty*8 + r][k]);
            fma2(accxy[r], wxy, xv);
            fma2(acczw[r], wzw, xv);
        }
    }

    float4 alv = *reinterpret_cast<const float4*>(a_l + tx*4);
    float4 arv = *reinterpret_cast<const float4*>(a_r + tx*4);
#pragma unroll
    for (int r = 0; r < 8; r++) {
        int g = r0 + ty*8 + r;
        float4 a;
        unpk2(accxy[r], a.x, a.y); unpk2(acczw[r], a.z, a.w);
        *reinterpret_cast<float4*>(&g_h[(size_t)g*DD + tx*4]) = a;
        float pl = a.x*alv.x + a.y*alv.y + a.z*alv.z + a.w*alv.w;
        float pr = a.x*arv.x + a.y*arv.y + a.z*arv.z + a.w*arv.w;
#pragma unroll
        for (int off = 16; off; off >>= 1) {
            pl += __shfl_down_sync(0xffffffffu, pl, off);
            pr += __shfl_down_sync(0xffffffffu, pr, off);
        }
        if (tx == 0) { g_el[g] = pl; g_er[g] = pr; }
    }

#pragma unroll 4
    for (int i = 0; i < 32; i++) {
        int g = r0 + i;
        if (nm[g] == 0) out[(size_t)g*DD + tid] = beta[tid];
    }
}

// ---------------- K3: compacted adjacency bitmask + hc + erc ----------------
__global__ void k3_adjc(const int* __restrict__ adj) {
    int b = blockIdx.y, ii = blockIdx.x;
    int cnt = g_cnt[b];
    int pad = (cnt + 31) & ~31;
    int tid = threadIdx.x;

    if (ii >= cnt) {
        if (ii < pad && tid < 32)
            *reinterpret_cast<float4*>(&g_hc[((size_t)b*NN + ii)*DD + tid*4]) =
                make_float4(0.f,0.f,0.f,0.f);
        return;
    }
    int i = g_act[b*NN + ii];
    if (tid < 32)
        *reinterpret_cast<float4*>(&g_hc[((size_t)b*NN + ii)*DD + tid*4]) =
        *reinterpret_cast<const float4*>(&g_h[((size_t)b*NN + i)*DD + tid*4]);
    if (ii == 0) {
        for (int jj = tid; jj < cnt; jj += 256)
            g_erc[b*NN + jj] = g_er[b*NN + g_act[b*NN + jj]];
    }

    const int* arow = adj + ((size_t)b*NN + i)*NN;
    int lane = tid & 31, wid = tid >> 5;
    unsigned* dst = g_adjc + ((size_t)b*NN + ii)*NW;
    for (int jj0 = wid*32; jj0 < pad; jj0 += 256) {
        int jj = jj0 + lane;
        int a = 0;
        if (jj < cnt) a = arow[g_act[b*NN + jj]];
        unsigned bits = __ballot_sync(0xffffffffu, a != 0);
        if (lane == 0) dst[jj0 >> 5] = bits;
    }
}

// ---------------- K4: tensor-core P@H split partials ------------------------
// block = 128 thr (4 warps). Tile: 64 i-rows x 128 d. Warps split d (32 each).
// j processed in chunks of 32 (4 k-steps of 8) over this split's range.
__global__ __launch_bounds__(128) void k4_attn(void)
{
    __shared__ unsigned Pp[64][36];    // pair-permuted tf32 p
    __shared__ unsigned Hs[32][132];   // tf32 h chunk, row-major
    __shared__ float    ers[32];

    int b   = blockIdx.z;
    int sid = blockIdx.y;
    int cnt = g_cnt[b];
    int base = blockIdx.x * 64;
    if (base >= cnt) return;

    int tid = threadIdx.x;
    int lane = tid & 31, wid = tid >> 5;
    int gid = lane >> 2, tig = lane & 3;

    int nch = (cnt + 31) >> 5;
    int cs  = (nch + SPLIT - 1) / SPLIT;
    int jc0 = sid * cs;
    int jc1 = min(nch, jc0 + cs);

    // staging roles
    int prow = tid >> 1;                 // P row this thread stages (0..63)
    int jseg = (tid & 1) * 16;
    int iw   = min(base + prow, cnt - 1);
    float elv = g_el[b*NN + g_act[b*NN + iw]];
    const unsigned* adjrow = g_adjc + ((size_t)(b*NN) + iw)*NW;

    int hrow = tid >> 2;                 // H row this thread stages (0..31)
    int hseg = (tid & 3) * 32;
    const float* hcb = g_hc + (size_t)b*NN*DD;
    const float* ercb = g_erc + b*NN;

    float4 acc[4][4];
#pragma unroll
    for (int mt = 0; mt < 4; mt++)
#pragma unroll
        for (int nt = 0; nt < 4; nt++) acc[mt][nt] = make_float4(0.f,0.f,0.f,0.f);
    float psum = 0.f;

    int wd = wid * 32;

    for (int jc = jc0; jc < jc1; jc++) {
        __syncthreads();
        // stage er
        if (tid < 32) ers[tid] = ercb[jc*32 + tid];
        // stage H chunk (tf32)
        {
            const float4* src = reinterpret_cast<const float4*>(
                hcb + ((size_t)jc*32 + hrow)*DD + hseg);
#pragma unroll
            for (int q = 0; q < 8; q++) {
                float4 v = src[q];
                uint4 u = make_uint4(cvt_tf32(v.x), cvt_tf32(v.y),
                                     cvt_tf32(v.z), cvt_tf32(v.w));
                *reinterpret_cast<uint4*>(&Hs[hrow][hseg + q*4]) = u;
            }
        }
        __syncthreads();   // ers visible before P staging uses it
        // stage P chunk (exact fp32 p -> psum; tf32 bits -> smem, pair-permuted)
        {
            unsigned w = adjrow[jc];
#pragma unroll
            for (int q = 0; q < 16; q++) {
                int jl = jseg + q;
                float s = elv + ers[jl];
                s = (s > 0.f) ? s : ALPHA*s;
                float p = ((w >> jl) & 1u) ? exp2f(s*LOG2E) : 0.f;
                psum += p;
                int perm = (jl & 24) + ((jl & 3) << 1) + ((jl & 7) >> 2);
                Pp[prow][perm] = cvt_tf32(p);
            }
        }
        __syncthreads();

        // mma over 4 k-steps
#pragma unroll
        for (int ks = 0; ks < 4; ks++) {
            int kr = ks*8 + tig;
            unsigned b0[4], b1[4];
#pragma unroll
            for (int nt = 0; nt < 4; nt++) {
                int n = wd + nt*8 + gid;
                b0[nt] = Hs[kr][n];
                b1[nt] = Hs[kr + 4][n];
            }
#pragma unroll
            for (int mt = 0; mt < 4; mt++) {
                int row = mt*16 + gid;
                uint2 a02 = *reinterpret_cast<const uint2*>(&Pp[row][ks*8 + 2*tig]);
                uint2 a13 = *reinterpret_cast<const uint2*>(&Pp[row+8][ks*8 + 2*tig]);
#pragma unroll
                for (int nt = 0; nt < 4; nt++)
                    mma_tf32(acc[mt][nt], a02.x, a13.x, a02.y, a13.y, b0[nt], b1[nt]);
            }
        }
    }

    // psum: combine the two half-row partials (even + odd, fixed order)
    {
        float other = __shfl_xor_sync(0xffffffffu, psum, 1);
        if ((tid & 1) == 0) {
            int ii = base + prow;
            if (ii < NN) g_psumP[sid][b*NN + ii] = psum + other;
        }
    }

    // store AV partials
    float* pb = g_pacc + (size_t)sid*BB*NN*DD + (size_t)b*NN*DD;
#pragma unroll
    for (int mt = 0; mt < 4; mt++) {
        int i0 = base + mt*16 + gid;
#pragma unroll
        for (int nt = 0; nt < 4; nt++) {
            int d0 = wd + nt*8 + 2*tig;
            *reinterpret_cast<float2*>(&pb[(size_t)i0*DD + d0]) =
                make_float2(acc[mt][nt].x, acc[mt][nt].y);
            *reinterpret_cast<float2*>(&pb[(size_t)(i0+8)*DD + d0]) =
                make_float2(acc[mt][nt].z, acc[mt][nt].w);
        }
    }
}

// ---------------- K5: reduce splits + normalize + residual + LayerNorm ------
__global__ __launch_bounds__(128) void k5_finish(
    const float* __restrict__ x, const float* __restrict__ gamma,
    const float* __restrict__ beta, float* __restrict__ out)
{
    int b = blockIdx.y;
    int cnt = g_cnt[b];
    int lane = threadIdx.x & 31, wid = threadIdx.x >> 5;
    int base_ii = blockIdx.x * 32 + wid * 8;
    if (base_ii >= cnt) return;

    float4 gv = *reinterpret_cast<const float4*>(gamma + lane*4);
    float4 bv = *reinterpret_cast<const float4*>(beta  + lane*4);

#pragma unroll
    for (int r = 0; r < 8; r++) {
        int ii = base_ii + r;
        if (ii >= cnt) break;
        int g = b*NN + g_act[b*NN + ii];

        float4 a = make_float4(0.f,0.f,0.f,0.f);
        float tot = 0.f;
#pragma unroll
        for (int s = 0; s < SPLIT; s++) {
            const float4* pp = reinterpret_cast<const float4*>(
                g_pacc + (size_t)s*BB*NN*DD + ((size_t)b*NN + ii)*DD);
            float4 t = pp[lane];
            a.x += t.x; a.y += t.y; a.z += t.z; a.w += t.w;
            tot += g_psumP[s][b*NN + ii];
        }

        float inv;
        if (tot > 0.f) {
            inv = 1.f / tot;
        } else {
            a = make_float4(0.f,0.f,0.f,0.f);
            const float* hcb = g_hc + (size_t)b*NN*DD + lane*4;
            for (int jj = 0; jj < cnt; jj++) {
                float4 h4 = *reinterpret_cast<const float4*>(hcb + (size_t)jj*DD);
                a.x += h4.x; a.y += h4.y; a.z += h4.z; a.w += h4.w;
            }
            inv = 1.f / (float)NN;
        }

        float4 x4 = *reinterpret_cast<const float4*>(x + (size_t)g*DD + lane*4);
        float4 v;
        v.x = a.x*inv + x4.x;  v.y = a.y*inv + x4.y;
        v.z = a.z*inv + x4.z;  v.w = a.w*inv + x4.w;
        float s1 = v.x + v.y + v.z + v.w;
        float s2 = v.x*v.x + v.y*v.y + v.z*v.z + v.w*v.w;
#pragma unroll
        for (int off = 16; off; off >>= 1) {
            s1 += __shfl_xor_sync(0xffffffffu, s1, off);
            s2 += __shfl_xor_sync(0xffffffffu, s2, off);
        }
        float mu  = s1 * (1.f/128.f);
        float var = s2 * (1.f/128.f) - mu*mu;
        float rs  = rsqrtf(var + 1e-5f);
        float4 o;
        o.x = (v.x - mu)*rs*gv.x + bv.x;
        o.y = (v.y - mu)*rs*gv.y + bv.y;
        o.z = (v.z - mu)*rs*gv.z + bv.z;
        o.w = (v.w - mu)*rs*gv.w + bv.w;
        *reinterpret_cast<float4*>(out + (size_t)g*DD + lane*4) = o;
    }
}

// ---------------- launcher ---------------------------------------------------
extern "C" void kernel_launch(void* const* d_in, const int* in_sizes, int n_in,
                              void* d_out, int out_size) {
    const float* x     = (const float*)d_in[0];
    const int*   adj   = (const int*)  d_in[1];
    const int*   nm    = (const int*)  d_in[2];
    const float* W     = (const float*)d_in[3];
    const float* a_l   = (const float*)d_in[4];
    const float* a_r   = (const float*)d_in[5];
    const float* gamma = (const float*)d_in[6];
    const float* beta  = (const float*)d_in[7];
    float* out = (float*)d_out;

    k1_compact<<<BB, 256>>>(nm);
    k2_gemm<<<(BB*NN)/32, 128>>>(x, nm, W, a_l, a_r, beta, out);
    k3_adjc<<<dim3(NN, BB), 256>>>(adj);
    k4_attn<<<dim3(NN/64, SPLIT, BB), 128>>>();
    k5_finish<<<dim3(NN/32, BB), 128>>>(x, gamma, beta, out);
}

// round 5
// speedup vs baseline: 1.7623x; 1.1747x over previous
#include <cuda_runtime.h>
#include <cuda_bf16.h>
#include <cstdint>

#define BB 8
#define NN 2048
#define DD 128
#define ALPHA 0.2f
#define LOG2E 1.44269504f
#define NW (NN/32)
#define SPLIT 4

// ---------------- device scratch ----------------
__device__ float    g_h  [BB*NN*DD];
__device__ float    g_hc [BB*NN*DD];            // compacted h (zero-padded to 32)
__device__ float    g_el [BB*NN];
__device__ float    g_er [BB*NN];
__device__ float    g_erc[BB*NN];
__device__ int      g_act[BB*NN];
__device__ int      g_cnt[BB];
__device__ unsigned g_adjc[(size_t)BB*NN*NW];
__device__ float    g_pacc[(size_t)SPLIT*BB*NN*DD];
__device__ float    g_psumP[SPLIT][BB*NN];

// ---- mma / ldmatrix helpers ----
__device__ __forceinline__ void ldsm_x4(unsigned& r0, unsigned& r1,
                                        unsigned& r2, unsigned& r3, unsigned addr) {
    asm volatile("ldmatrix.sync.aligned.m8n8.x4.shared.b16 {%0,%1,%2,%3}, [%4];"
                 : "=r"(r0), "=r"(r1), "=r"(r2), "=r"(r3) : "r"(addr));
}
__device__ __forceinline__ void ldsm_x4_t(unsigned& r0, unsigned& r1,
                                          unsigned& r2, unsigned& r3, unsigned addr) {
    asm volatile("ldmatrix.sync.aligned.m8n8.x4.trans.shared.b16 {%0,%1,%2,%3}, [%4];"
                 : "=r"(r0), "=r"(r1), "=r"(r2), "=r"(r3) : "r"(addr));
}
__device__ __forceinline__ void mma_bf16(float4& d, unsigned a0, unsigned a1,
                                         unsigned a2, unsigned a3,
                                         unsigned b0, unsigned b1) {
    asm volatile("mma.sync.aligned.m16n8k16.row.col.f32.bf16.bf16.f32 "
        "{%0,%1,%2,%3}, {%4,%5,%6,%7}, {%8,%9}, {%0,%1,%2,%3};"
        : "+f"(d.x), "+f"(d.y), "+f"(d.z), "+f"(d.w)
        : "r"(a0), "r"(a1), "r"(a2), "r"(a3), "r"(b0), "r"(b1));
}

// ---------------- K1: deterministic compaction ----------------
__global__ void k1_compact(const int* __restrict__ nm) {
    int b = blockIdx.x, t = threadIdx.x;
    __shared__ int part[256];
    const int* m = nm + b*NN;
    int base = t*8, flags[8], c = 0;
#pragma unroll
    for (int k = 0; k < 8; k++) { flags[k] = (m[base+k] != 0); c += flags[k]; }
    part[t] = c; __syncthreads();
    for (int off = 1; off < 256; off <<= 1) {
        int add = (t >= off) ? part[t-off] : 0;
        __syncthreads(); part[t] += add; __syncthreads();
    }
    int pos = part[t] - c;
#pragma unroll
    for (int k = 0; k < 8; k++) if (flags[k]) { g_act[b*NN + pos] = base + k; pos++; }
    if (t == 255) g_cnt[b] = part[255];
}

// ---------------- K2: h=(x*m)@W (scalar fp32, R3 form), e_l/e_r -------------
__global__ __launch_bounds__(128) void k2_gemm(
    const float* __restrict__ x, const int* __restrict__ nm,
    const float* __restrict__ W, const float* __restrict__ a_l,
    const float* __restrict__ a_r, const float* __restrict__ beta,
    float* __restrict__ out)
{
    __shared__ float xs[32][DD];
    int tid = threadIdx.x, tx = tid & 31, ty = tid >> 5;
    int r0 = blockIdx.x * 32;

#pragma unroll 4
    for (int i = 0; i < 32; i++) {
        int g = r0 + i;
        float mv = (nm[g] != 0) ? 1.f : 0.f;
        xs[i][tid] = x[(size_t)g*DD + tid] * mv;
    }
    __syncthreads();

    float4 acc[8];
#pragma unroll
    for (int r = 0; r < 8; r++) acc[r] = make_float4(0.f,0.f,0.f,0.f);

    const float4* W4 = reinterpret_cast<const float4*>(W);
#pragma unroll 4
    for (int k = 0; k < DD; k++) {
        float4 w4 = W4[k*32 + tx];
#pragma unroll
        for (int r = 0; r < 8; r++) {
            float xv = xs[ty*8 + r][k];
            acc[r].x += xv*w4.x; acc[r].y += xv*w4.y;
            acc[r].z += xv*w4.z; acc[r].w += xv*w4.w;
        }
    }

    float4 alv = *reinterpret_cast<const float4*>(a_l + tx*4);
    float4 arv = *reinterpret_cast<const float4*>(a_r + tx*4);
#pragma unroll
    for (int r = 0; r < 8; r++) {
        int g = r0 + ty*8 + r;
        *reinterpret_cast<float4*>(&g_h[(size_t)g*DD + tx*4]) = acc[r];
        float pl = acc[r].x*alv.x + acc[r].y*alv.y + acc[r].z*alv.z + acc[r].w*alv.w;
        float pr = acc[r].x*arv.x + acc[r].y*arv.y + acc[r].z*arv.z + acc[r].w*arv.w;
#pragma unroll
        for (int off = 16; off; off >>= 1) {
            pl += __shfl_down_sync(0xffffffffu, pl, off);
            pr += __shfl_down_sync(0xffffffffu, pr, off);
        }
        if (tx == 0) { g_el[g] = pl; g_er[g] = pr; }
    }

#pragma unroll 4
    for (int i = 0; i < 32; i++) {
        int g = r0 + i;
        if (nm[g] == 0) out[(size_t)g*DD + tid] = beta[tid];
    }
}

// ---------------- K3: compacted adjacency bitmask + hc + erc ----------------
__global__ void k3_adjc(const int* __restrict__ adj) {
    int b = blockIdx.y, ii = blockIdx.x;
    int cnt = g_cnt[b];
    int pad = (cnt + 31) & ~31;
    int tid = threadIdx.x;

    if (ii >= cnt) {
        if (ii < pad && tid < 32)
            *reinterpret_cast<float4*>(&g_hc[((size_t)b*NN + ii)*DD + tid*4]) =
                make_float4(0.f,0.f,0.f,0.f);
        return;
    }
    int i = g_act[b*NN + ii];
    if (tid < 32)
        *reinterpret_cast<float4*>(&g_hc[((size_t)b*NN + ii)*DD + tid*4]) =
        *reinterpret_cast<const float4*>(&g_h[((size_t)b*NN + i)*DD + tid*4]);
    if (ii == 0) {
        for (int jj = tid; jj < cnt; jj += 256)
            g_erc[b*NN + jj] = g_er[b*NN + g_act[b*NN + jj]];
    }

    const int* arow = adj + ((size_t)b*NN + i)*NN;
    int lane = tid & 31, wid = tid >> 5;
    unsigned* dst = g_adjc + ((size_t)b*NN + ii)*NW;
    for (int jj0 = wid*32; jj0 < pad; jj0 += 256) {
        int jj = jj0 + lane;
        int a = 0;
        if (jj < cnt) a = arow[g_act[b*NN + jj]];
        unsigned bits = __ballot_sync(0xffffffffu, a != 0);
        if (lane == 0) dst[jj0 >> 5] = bits;
    }
}

// ---------------- K4: bf16 tensor-core P@H split partials -------------------
// block = 128 thr (4 warps). Tile: 64 i x 128 d; warps split d (32 each).
// j chunks of 32 = 2 mma k-steps of 16. A/B fragments via ldmatrix.x4.
__global__ __launch_bounds__(128) void k4_attn(void)
{
    __shared__ __align__(16) __nv_bfloat16 Pp[64][40];   // 80B rows (pad 8)
    __shared__ __align__(16) __nv_bfloat16 Hs[32][136];  // 272B rows (pad 8)

    int b   = blockIdx.z;
    int sid = blockIdx.y;
    int cnt = g_cnt[b];
    int base = blockIdx.x * 64;
    if (base >= cnt) return;

    int tid = threadIdx.x, lane = tid & 31, wid = tid >> 5;
    int wd = wid * 32;

    int nch = (cnt + 31) >> 5;
    int cs  = (nch + SPLIT - 1) / SPLIT;
    int jc0 = sid * cs;
    int jc1 = min(nch, jc0 + cs);

    // staging roles
    int prow = tid >> 1;                  // P row (0..63), 2 threads/row
    int jseg = (tid & 1) * 16;
    int iw   = min(base + prow, cnt - 1);
    float elv = g_el[b*NN + g_act[b*NN + iw]];
    const unsigned* adjrow = g_adjc + ((size_t)(b*NN) + iw)*NW;

    int hrow = tid >> 2;                  // H row (0..31), 4 threads/row
    int hseg = (tid & 3) * 32;
    const float* hcb  = g_hc  + (size_t)b*NN*DD;
    const float* ercb = g_erc + b*NN;

    float4 acc[4][4];
#pragma unroll
    for (int mt = 0; mt < 4; mt++)
#pragma unroll
        for (int nt = 0; nt < 4; nt++) acc[mt][nt] = make_float4(0.f,0.f,0.f,0.f);
    float psum = 0.f;

    unsigned Pb = (unsigned)__cvta_generic_to_shared(&Pp[0][0]);
    unsigned Hb = (unsigned)__cvta_generic_to_shared(&Hs[0][0]);
    // A ldmatrix lane address: row = lane&15, k-block = (lane>>4)&1
    unsigned aaddr0 = Pb + (unsigned)((lane & 15)*80 + ((lane >> 4) & 1)*16);
    // B ldmatrix lane address: m = lane>>3; row = (m&1)*8 + lane&7; n-block = m>>1
    unsigned baddr0 = Hb + (unsigned)((((lane >> 3) & 1)*8 + (lane & 7))*272
                                      + (wd + ((lane >> 4) & 1)*8)*2);

    for (int jc = jc0; jc < jc1; jc++) {
        __syncthreads();
        // ---- stage H chunk -> bf16 row-major Hs[j][d] ----
        {
            const float4* src = reinterpret_cast<const float4*>(
                hcb + ((size_t)(jc*32 + hrow))*DD + hseg);
#pragma unroll
            for (int q = 0; q < 4; q++) {
                float4 v0 = src[q*2], v1 = src[q*2+1];
                __nv_bfloat162 w0 = __float22bfloat162_rn(make_float2(v0.x, v0.y));
                __nv_bfloat162 w1 = __float22bfloat162_rn(make_float2(v0.z, v0.w));
                __nv_bfloat162 w2 = __float22bfloat162_rn(make_float2(v1.x, v1.y));
                __nv_bfloat162 w3 = __float22bfloat162_rn(make_float2(v1.z, v1.w));
                uint4 u = make_uint4(*(unsigned*)&w0, *(unsigned*)&w1,
                                     *(unsigned*)&w2, *(unsigned*)&w3);
                *reinterpret_cast<uint4*>(&Hs[hrow][hseg + q*8]) = u;
            }
        }
        // ---- stage P chunk (consistent bf16 rounding; psum over rounded) ----
        {
            unsigned w = adjrow[jc];
            const float4* er4 = reinterpret_cast<const float4*>(ercb + jc*32 + jseg);
            float ev[16];
#pragma unroll
            for (int q4 = 0; q4 < 4; q4++) {
                float4 e = er4[q4];
                ev[q4*4+0] = e.x; ev[q4*4+1] = e.y; ev[q4*4+2] = e.z; ev[q4*4+3] = e.w;
            }
            __nv_bfloat162 pw[8];
#pragma unroll
            for (int q = 0; q < 8; q++) {
                float p2[2];
#pragma unroll
                for (int h = 0; h < 2; h++) {
                    int jl = jseg + q*2 + h;
                    float s = elv + ev[q*2 + h];
                    s = (s > 0.f) ? s : ALPHA*s;
                    p2[h] = ((w >> jl) & 1u) ? exp2f(s*LOG2E) : 0.f;
                }
                __nv_bfloat162 pb = __float22bfloat162_rn(make_float2(p2[0], p2[1]));
                pw[q] = pb;
                float2 pr = __bfloat1622float2(pb);
                psum += pr.x + pr.y;
            }
            *reinterpret_cast<uint4*>(&Pp[prow][jseg]) =
                make_uint4(*(unsigned*)&pw[0], *(unsigned*)&pw[1],
                           *(unsigned*)&pw[2], *(unsigned*)&pw[3]);
            *reinterpret_cast<uint4*>(&Pp[prow][jseg + 8]) =
                make_uint4(*(unsigned*)&pw[4], *(unsigned*)&pw[5],
                           *(unsigned*)&pw[6], *(unsigned*)&pw[7]);
        }
        __syncthreads();

        // ---- mma: 2 k-steps x 4 mt x 4 nt ----
#pragma unroll
        for (int ks = 0; ks < 2; ks++) {
            unsigned bf[8];
            ldsm_x4_t(bf[0], bf[1], bf[2], bf[3], baddr0 + ks*4352u);
            ldsm_x4_t(bf[4], bf[5], bf[6], bf[7], baddr0 + ks*4352u + 32u);
#pragma unroll
            for (int mt = 0; mt < 4; mt++) {
                unsigned a0, a1, a2, a3;
                ldsm_x4(a0, a1, a2, a3, aaddr0 + (unsigned)(mt*1280 + ks*32));
                mma_bf16(acc[mt][0], a0,a1,a2,a3, bf[0], bf[1]);
                mma_bf16(acc[mt][1], a0,a1,a2,a3, bf[2], bf[3]);
                mma_bf16(acc[mt][2], a0,a1,a2,a3, bf[4], bf[5]);
                mma_bf16(acc[mt][3], a0,a1,a2,a3, bf[6], bf[7]);
            }
        }
    }

    // psum: combine two half-rows (fixed order: even lane + odd lane)
    {
        float other = __shfl_xor_sync(0xffffffffu, psum, 1);
        if ((tid & 1) == 0) {
            int ii = base + prow;
            g_psumP[sid][b*NN + ii] = psum + other;
        }
    }

    // store AV partials
    int gid = lane >> 2, tig = lane & 3;
    float* pb = g_pacc + (size_t)sid*BB*NN*DD + (size_t)b*NN*DD;
#pragma unroll
    for (int mt = 0; mt < 4; mt++) {
        int i0 = base + mt*16 + gid;
#pragma unroll
        for (int nt = 0; nt < 4; nt++) {
            int d0 = wd + nt*8 + 2*tig;
            *reinterpret_cast<float2*>(&pb[(size_t)i0*DD + d0]) =
                make_float2(acc[mt][nt].x, acc[mt][nt].y);
            *reinterpret_cast<float2*>(&pb[(size_t)(i0+8)*DD + d0]) =
                make_float2(acc[mt][nt].z, acc[mt][nt].w);
        }
    }
}

// ---------------- K5: reduce splits + normalize + residual + LayerNorm ------
__global__ __launch_bounds__(128) void k5_finish(
    const float* __restrict__ x, const float* __restrict__ gamma,
    const float* __restrict__ beta, float* __restrict__ out)
{
    int b = blockIdx.y;
    int cnt = g_cnt[b];
    int lane = threadIdx.x & 31, wid = threadIdx.x >> 5;
    int base_ii = blockIdx.x * 8 + wid * 2;
    if (base_ii >= cnt) return;

    float4 gv = *reinterpret_cast<const float4*>(gamma + lane*4);
    float4 bv = *reinterpret_cast<const float4*>(beta  + lane*4);

#pragma unroll
    for (int r = 0; r < 2; r++) {
        int ii = base_ii + r;
        if (ii >= cnt) continue;
        int g = b*NN + g_act[b*NN + ii];

        float4 a = make_float4(0.f,0.f,0.f,0.f);
        float tot = 0.f;
#pragma unroll
        for (int s = 0; s < SPLIT; s++) {
            const float4* pp = reinterpret_cast<const float4*>(
                g_pacc + (size_t)s*BB*NN*DD + ((size_t)b*NN + ii)*DD);
            float4 t = pp[lane];
            a.x += t.x; a.y += t.y; a.z += t.z; a.w += t.w;
            tot += g_psumP[s][b*NN + ii];
        }

        float inv;
        if (tot > 0.f) {
            inv = 1.f / tot;
        } else {
            a = make_float4(0.f,0.f,0.f,0.f);
            const float* hcb = g_hc + (size_t)b*NN*DD + lane*4;
            for (int jj = 0; jj < cnt; jj++) {
                float4 h4 = *reinterpret_cast<const float4*>(hcb + (size_t)jj*DD);
                a.x += h4.x; a.y += h4.y; a.z += h4.z; a.w += h4.w;
            }
            inv = 1.f / (float)NN;
        }

        float4 x4 = *reinterpret_cast<const float4*>(x + (size_t)g*DD + lane*4);
        float4 v;
        v.x = a.x*inv + x4.x;  v.y = a.y*inv + x4.y;
        v.z = a.z*inv + x4.z;  v.w = a.w*inv + x4.w;
        float s1 = v.x + v.y + v.z + v.w;
        float s2 = v.x*v.x + v.y*v.y + v.z*v.z + v.w*v.w;
#pragma unroll
        for (int off = 16; off; off >>= 1) {
            s1 += __shfl_xor_sync(0xffffffffu, s1, off);
            s2 += __shfl_xor_sync(0xffffffffu, s2, off);
        }
        float mu  = s1 * (1.f/128.f);
        float var = s2 * (1.f/128.f) - mu*mu;
        float rs  = rsqrtf(var + 1e-5f);
        float4 o;
        o.x = (v.x - mu)*rs*gv.x + bv.x;
        o.y = (v.y - mu)*rs*gv.y + bv.y;
        o.z = (v.z - mu)*rs*gv.z + bv.z;
        o.w = (v.w - mu)*rs*gv.w + bv.w;
        *reinterpret_cast<float4*>(out + (size_t)g*DD + lane*4) = o;
    }
}

// ---------------- launcher ---------------------------------------------------
extern "C" void kernel_launch(void* const* d_in, const int* in_sizes, int n_in,
                              void* d_out, int out_size) {
    const float* x     = (const float*)d_in[0];
    const int*   adj   = (const int*)  d_in[1];
    const int*   nm    = (const int*)  d_in[2];
    const float* W     = (const float*)d_in[3];
    const float* a_l   = (const float*)d_in[4];
    const float* a_r   = (const float*)d_in[5];
    const float* gamma = (const float*)d_in[6];
    const float* beta  = (const float*)d_in[7];
    float* out = (float*)d_out;

    k1_compact<<<BB, 256>>>(nm);
    k2_gemm<<<(BB*NN)/32, 128>>>(x, nm, W, a_l, a_r, beta, out);
    k3_adjc<<<dim3(NN, BB), 256>>>(adj);
    k4_attn<<<dim3(NN/64, SPLIT, BB), 128>>>();
    k5_finish<<<dim3(NN/8, BB), 128>>>(x, gamma, beta, out);
}

// round 6
// speedup vs baseline: 2.2493x; 1.2763x over previous
#include <cuda_runtime.h>
#include <cuda_bf16.h>
#include <cstdint>

#define BB 8
#define NN 2048
#define DD 128
#define LOG2E 1.44269504f
#define NW (NN/32)
#define SPLIT 4
#define PSTR 40      // P smem row stride (bf16 units)
#define HSTR 136     // H smem row stride (bf16 units)
#define PBUFB (64*PSTR*2)   // 5120 B per P buffer
#define HBUFB (32*HSTR*2)   // 8704 B per H buffer

// ---------------- device scratch ----------------
__device__ unsigned short g_hcb [BB*NN*DD];   // compacted h, bf16 (padded rows stay 0)
__device__ unsigned       g_eln [BB*NN];      // packed (bf16 exp(.2el) << 16) | bf16 exp(el)
__device__ unsigned short g_er1c[BB*NN];      // bf16 exp(er)      (padded stay 0)
__device__ unsigned short g_er2c[BB*NN];      // bf16 exp(.2 er)
__device__ int            g_act [BB*NN];
__device__ int            g_posm[BB*NN];      // node -> compacted pos (or -1)
__device__ int            g_cnt [BB];
__device__ unsigned       g_adjc[(size_t)BB*NN*NW];
__device__ float          g_pacc[(size_t)SPLIT*BB*NN*DD];
__device__ float          g_psumP[SPLIT][BB*NN];

// ---- helpers ----
__device__ __forceinline__ unsigned hmul2u(unsigned a, unsigned b) {
    __nv_bfloat162 r = __hmul2(*reinterpret_cast<__nv_bfloat162*>(&a),
                               *reinterpret_cast<__nv_bfloat162*>(&b));
    return *reinterpret_cast<unsigned*>(&r);
}
__device__ __forceinline__ unsigned hmax2u(unsigned a, unsigned b) {
    __nv_bfloat162 r = __hmax2(*reinterpret_cast<__nv_bfloat162*>(&a),
                               *reinterpret_cast<__nv_bfloat162*>(&b));
    return *reinterpret_cast<unsigned*>(&r);
}
__device__ __forceinline__ unsigned bpack(float x, float y) {
    __nv_bfloat162 r = __float22bfloat162_rn(make_float2(x, y));
    return *reinterpret_cast<unsigned*>(&r);
}
__device__ __forceinline__ void ldsm_x4(unsigned& r0, unsigned& r1,
                                        unsigned& r2, unsigned& r3, unsigned addr) {
    asm volatile("ldmatrix.sync.aligned.m8n8.x4.shared.b16 {%0,%1,%2,%3}, [%4];"
                 : "=r"(r0), "=r"(r1), "=r"(r2), "=r"(r3) : "r"(addr));
}
__device__ __forceinline__ void ldsm_x4_t(unsigned& r0, unsigned& r1,
                                          unsigned& r2, unsigned& r3, unsigned addr) {
    asm volatile("ldmatrix.sync.aligned.m8n8.x4.trans.shared.b16 {%0,%1,%2,%3}, [%4];"
                 : "=r"(r0), "=r"(r1), "=r"(r2), "=r"(r3) : "r"(addr));
}
__device__ __forceinline__ void mma_bf16(float4& d, unsigned a0, unsigned a1,
                                         unsigned a2, unsigned a3,
                                         unsigned b0, unsigned b1) {
    asm volatile("mma.sync.aligned.m16n8k16.row.col.f32.bf16.bf16.f32 "
        "{%0,%1,%2,%3}, {%4,%5,%6,%7}, {%8,%9}, {%0,%1,%2,%3};"
        : "+f"(d.x), "+f"(d.y), "+f"(d.z), "+f"(d.w)
        : "r"(a0), "r"(a1), "r"(a2), "r"(a3), "r"(b0), "r"(b1));
}
#define CP_ASYNC16(dst, src) \
    asm volatile("cp.async.cg.shared.global [%0], [%1], 16;" :: "r"(dst), "l"(src))
#define CP_COMMIT asm volatile("cp.async.commit_group;" ::: "memory")
#define CP_WAIT0  asm volatile("cp.async.wait_group 0;" ::: "memory")

// ---------------- K1: deterministic compaction ----------------
__global__ void k1_compact(const int* __restrict__ nm) {
    int b = blockIdx.x, t = threadIdx.x;
    __shared__ int part[256];
    const int* m = nm + b*NN;
    int base = t*8, flags[8], c = 0;
#pragma unroll
    for (int k = 0; k < 8; k++) { flags[k] = (m[base+k] != 0); c += flags[k]; }
    part[t] = c; __syncthreads();
    for (int off = 1; off < 256; off <<= 1) {
        int add = (t >= off) ? part[t-off] : 0;
        __syncthreads(); part[t] += add; __syncthreads();
    }
    int pos = part[t] - c;
#pragma unroll
    for (int k = 0; k < 8; k++) {
        if (flags[k]) { g_act[b*NN + pos] = base + k; g_posm[b*NN + base + k] = pos; pos++; }
        else g_posm[b*NN + base + k] = -1;
    }
    if (t == 255) g_cnt[b] = part[255];
}

// ---------------- K2: h=(x*m)@W; write bf16 hcb + exp factors ---------------
__global__ __launch_bounds__(128) void k2_gemm(
    const float* __restrict__ x, const int* __restrict__ nm,
    const float* __restrict__ W, const float* __restrict__ a_l,
    const float* __restrict__ a_r, const float* __restrict__ beta,
    float* __restrict__ out)
{
    __shared__ float xs[32][DD];
    int tid = threadIdx.x, tx = tid & 31, ty = tid >> 5;
    int r0 = blockIdx.x * 32;
    int b = r0 / NN;

#pragma unroll 4
    for (int i = 0; i < 32; i++) {
        int g = r0 + i;
        float mv = (nm[g] != 0) ? 1.f : 0.f;
        xs[i][tid] = x[(size_t)g*DD + tid] * mv;
    }
    __syncthreads();

    float4 acc[8];
#pragma unroll
    for (int r = 0; r < 8; r++) acc[r] = make_float4(0.f,0.f,0.f,0.f);

    const float4* W4 = reinterpret_cast<const float4*>(W);
#pragma unroll 4
    for (int k = 0; k < DD; k++) {
        float4 w4 = W4[k*32 + tx];
#pragma unroll
        for (int r = 0; r < 8; r++) {
            float xv = xs[ty*8 + r][k];
            acc[r].x += xv*w4.x; acc[r].y += xv*w4.y;
            acc[r].z += xv*w4.z; acc[r].w += xv*w4.w;
        }
    }

    float4 alv = *reinterpret_cast<const float4*>(a_l + tx*4);
    float4 arv = *reinterpret_cast<const float4*>(a_r + tx*4);
#pragma unroll
    for (int r = 0; r < 8; r++) {
        int g = r0 + ty*8 + r;
        int pos = g_posm[g];
        if (pos >= 0) {
            uint2 hv = make_uint2(bpack(acc[r].x, acc[r].y), bpack(acc[r].z, acc[r].w));
            *reinterpret_cast<uint2*>(&g_hcb[(size_t)(b*NN + pos)*DD + tx*4]) = hv;
        }
        float pl = acc[r].x*alv.x + acc[r].y*alv.y + acc[r].z*alv.z + acc[r].w*alv.w;
        float pr = acc[r].x*arv.x + acc[r].y*arv.y + acc[r].z*arv.z + acc[r].w*arv.w;
#pragma unroll
        for (int off = 16; off; off >>= 1) {
            pl += __shfl_down_sync(0xffffffffu, pl, off);
            pr += __shfl_down_sync(0xffffffffu, pr, off);
        }
        if (tx == 0 && pos >= 0) {
            g_eln[b*NN + pos] = bpack(exp2f(pl*LOG2E), exp2f(0.2f*pl*LOG2E));
            __nv_bfloat16 r1 = __float2bfloat16(exp2f(pr*LOG2E));
            __nv_bfloat16 r2 = __float2bfloat16(exp2f(0.2f*pr*LOG2E));
            g_er1c[b*NN + pos] = *reinterpret_cast<unsigned short*>(&r1);
            g_er2c[b*NN + pos] = *reinterpret_cast<unsigned short*>(&r2);
        }
    }

    // masked rows -> output is exactly beta (out row==0 -> LN -> beta)
#pragma unroll 4
    for (int i = 0; i < 32; i++) {
        int g = r0 + i;
        if (nm[g] == 0) out[(size_t)g*DD + tid] = beta[tid];
    }
}

// ---------------- K3: compacted adjacency bitmask (4 rows/block) ------------
__global__ __launch_bounds__(256) void k3_adjc(const int* __restrict__ adj) {
    int b = blockIdx.y;
    int cnt = g_cnt[b];
    int pad = (cnt + 31) & ~31;
    int ii = blockIdx.x*4 + (threadIdx.x >> 6);
    if (ii >= cnt) return;
    int i = g_act[b*NN + ii];
    const int* arow = adj + ((size_t)b*NN + i)*NN;
    int lane = threadIdx.x & 31, half = (threadIdx.x >> 5) & 1;
    unsigned* dst = g_adjc + ((size_t)b*NN + ii)*NW;
    for (int jj0 = half*32; jj0 < pad; jj0 += 64) {
        int jj = jj0 + lane;
        int a = (jj < cnt) ? arow[g_act[b*NN + jj]] : 0;
        unsigned bits = __ballot_sync(0xffffffffu, a != 0);
        if (lane == 0) dst[jj0 >> 5] = bits;
    }
}

// ---------------- K4: exp-free bf16 tensor P@H + tensor psum ----------------
// 256 thr / 8 warps. Tile 64 i x 128 d. warp: mw=wid>>2 (32 rows), nw=wid&3 (32 d).
__device__ __forceinline__ unsigned pmix(unsigned El1, unsigned El2,
                                         unsigned e1, unsigned e2, unsigned m) {
    return hmax2u(hmul2u(El1, e1), hmul2u(El2, e2)) & m;
}

__global__ __launch_bounds__(256,3) void k4_attn(void)
{
    __shared__ __align__(16) unsigned short Pp[2][64][PSTR];
    __shared__ __align__(16) unsigned short Hs[2][32][HSTR];
    __shared__ unsigned lutm[4];

    int b = blockIdx.z, sid = blockIdx.y;
    int cnt = g_cnt[b];
    int base = blockIdx.x * 64;
    if (base >= cnt) return;

    int tid = threadIdx.x, lane = tid & 31, wid = tid >> 5;
    int mw = wid >> 2, nw = wid & 3, wd = nw*32;
    if (tid < 4) lutm[tid] = ((tid & 1) ? 0xFFFFu : 0u) | ((tid & 2) ? 0xFFFF0000u : 0u);

    int nch = (cnt + 31) >> 5;
    int cs  = (nch + SPLIT - 1) / SPLIT;
    int jc0 = sid * cs;
    int jc1 = min(nch, jc0 + cs);

    // P staging role: 4 thr/row, 8 j each
    int prow = tid >> 2, jq = (tid & 3) * 8;
    int iw = min(base + prow, cnt - 1);
    unsigned eln = g_eln[b*NN + iw];
    unsigned El1 = __byte_perm(eln, eln, 0x1010);   // dup low bf16 (exp(el))
    unsigned El2 = __byte_perm(eln, eln, 0x3232);   // dup high bf16 (exp(.2el))
    const unsigned* adjp = g_adjc + ((size_t)b*NN + iw)*NW;
    const unsigned short* er1b = g_er1c + b*NN;
    const unsigned short* er2b = g_er2c + b*NN;

    // H staging role: 8 thr/row, 16 bf16 (32B = 2 cp.async) each
    int hrow = tid >> 3, hseg = (tid & 7) * 16;
    const unsigned short* hsrc0 = g_hcb + (size_t)b*NN*DD;

    float4 acc[2][4]; float4 ps[2];
#pragma unroll
    for (int mt = 0; mt < 2; mt++) {
        ps[mt] = make_float4(0.f,0.f,0.f,0.f);
#pragma unroll
        for (int nt = 0; nt < 4; nt++) acc[mt][nt] = make_float4(0.f,0.f,0.f,0.f);
    }

    unsigned Pbase = (unsigned)__cvta_generic_to_shared(&Pp[0][0][0]);
    unsigned Hbase = (unsigned)__cvta_generic_to_shared(&Hs[0][0][0]);
    unsigned aaddr = Pbase + (unsigned)((mw*32 + (lane & 15))*PSTR*2 + ((lane >> 4) & 1)*16);
    unsigned baddr = Hbase + (unsigned)(((((lane >> 3) & 1)*8) + (lane & 7))*HSTR*2
                                        + (wd + ((lane >> 4) & 1)*8)*2);
    unsigned pdst = Pbase + (unsigned)(prow*PSTR*2 + jq*2);
    unsigned hdst = Hbase + (unsigned)(hrow*HSTR*2 + hseg*2);
    const unsigned ONES = 0x3F803F80u;

    __syncthreads();   // lutm visible

    // ---- prologue: stage chunk jc0 into buffer 0 ----
    if (jc0 < jc1) {
        unsigned w = adjp[jc0] >> jq;
        uint4 e1 = *reinterpret_cast<const uint4*>(er1b + jc0*32 + jq);
        uint4 e2 = *reinterpret_cast<const uint4*>(er2b + jc0*32 + jq);
        uint4 o;
        o.x = pmix(El1, El2, e1.x, e2.x, lutm[w & 3]);
        o.y = pmix(El1, El2, e1.y, e2.y, lutm[(w >> 2) & 3]);
        o.z = pmix(El1, El2, e1.z, e2.z, lutm[(w >> 4) & 3]);
        o.w = pmix(El1, El2, e1.w, e2.w, lutm[(w >> 6) & 3]);
        asm volatile("st.shared.v4.b32 [%0], {%1,%2,%3,%4};"
                     :: "r"(pdst), "r"(o.x), "r"(o.y), "r"(o.z), "r"(o.w));
        const unsigned short* src = hsrc0 + ((size_t)(jc0*32 + hrow))*DD + hseg;
        CP_ASYNC16(hdst, src);
        CP_ASYNC16(hdst + 16, src + 8);
        CP_COMMIT;
    }

    for (int jc = jc0; jc < jc1; jc++) {
        int cur = (jc - jc0) & 1, nxt = cur ^ 1;
        CP_WAIT0;
        __syncthreads();   // cur fully staged; prev mma reads of nxt done

        if (jc + 1 < jc1) {   // stage next chunk (overlaps mma below)
            unsigned w = adjp[jc+1] >> jq;
            uint4 e1 = *reinterpret_cast<const uint4*>(er1b + (jc+1)*32 + jq);
            uint4 e2 = *reinterpret_cast<const uint4*>(er2b + (jc+1)*32 + jq);
            uint4 o;
            o.x = pmix(El1, El2, e1.x, e2.x, lutm[w & 3]);
            o.y = pmix(El1, El2, e1.y, e2.y, lutm[(w >> 2) & 3]);
            o.z = pmix(El1, El2, e1.z, e2.z, lutm[(w >> 4) & 3]);
            o.w = pmix(El1, El2, e1.w, e2.w, lutm[(w >> 6) & 3]);
            asm volatile("st.shared.v4.b32 [%0], {%1,%2,%3,%4};"
                         :: "r"(pdst + nxt*PBUFB), "r"(o.x), "r"(o.y), "r"(o.z), "r"(o.w));
            const unsigned short* src = hsrc0 + ((size_t)((jc+1)*32 + hrow))*DD + hseg;
            CP_ASYNC16(hdst + nxt*HBUFB, src);
            CP_ASYNC16(hdst + nxt*HBUFB + 16, src + 8);
            CP_COMMIT;
        }

        unsigned pa = aaddr + cur*PBUFB;
        unsigned hb = baddr + cur*HBUFB;
#pragma unroll
        for (int ks = 0; ks < 2; ks++) {
            unsigned bf[8];
            ldsm_x4_t(bf[0], bf[1], bf[2], bf[3], hb + ks*16*HSTR*2);
            ldsm_x4_t(bf[4], bf[5], bf[6], bf[7], hb + ks*16*HSTR*2 + 32);
            unsigned a0[4], a1[4];
            ldsm_x4(a0[0], a0[1], a0[2], a0[3], pa + ks*32);
            ldsm_x4(a1[0], a1[1], a1[2], a1[3], pa + 16*PSTR*2 + ks*32);
#pragma unroll
            for (int nt = 0; nt < 4; nt++) {
                mma_bf16(acc[0][nt], a0[0],a0[1],a0[2],a0[3], bf[nt*2], bf[nt*2+1]);
                mma_bf16(acc[1][nt], a1[0],a1[1],a1[2],a1[3], bf[nt*2], bf[nt*2+1]);
            }
            if (nw == 0) {
                mma_bf16(ps[0], a0[0],a0[1],a0[2],a0[3], ONES, ONES);
                mma_bf16(ps[1], a1[0],a1[1],a1[2],a1[3], ONES, ONES);
            }
        }
    }

    // ---- write psum partials (tensor-produced; cols identical) ----
    int gid = lane >> 2, tig = lane & 3;
    if (nw == 0 && tig == 0) {
#pragma unroll
        for (int mt = 0; mt < 2; mt++) {
            int i0 = base + mw*32 + mt*16 + gid;
            g_psumP[sid][b*NN + i0]     = ps[mt].x;
            g_psumP[sid][b*NN + i0 + 8] = ps[mt].z;
        }
    }

    // ---- store AV partials ----
    float* pb = g_pacc + (size_t)sid*BB*NN*DD + (size_t)b*NN*DD;
#pragma unroll
    for (int mt = 0; mt < 2; mt++) {
        int i0 = base + mw*32 + mt*16 + gid;
#pragma unroll
        for (int nt = 0; nt < 4; nt++) {
            int d0 = wd + nt*8 + 2*tig;
            *reinterpret_cast<float2*>(&pb[(size_t)i0*DD + d0]) =
                make_float2(acc[mt][nt].x, acc[mt][nt].y);
            *reinterpret_cast<float2*>(&pb[(size_t)(i0+8)*DD + d0]) =
                make_float2(acc[mt][nt].z, acc[mt][nt].w);
        }
    }
}

// ---------------- K5: reduce splits + normalize + residual + LayerNorm ------
__global__ __launch_bounds__(128) void k5_finish(
    const float* __restrict__ x, const float* __restrict__ gamma,
    const float* __restrict__ beta, float* __restrict__ out)
{
    int b = blockIdx.y;
    int cnt = g_cnt[b];
    int lane = threadIdx.x & 31, wid = threadIdx.x >> 5;
    int base_ii = blockIdx.x * 8 + wid * 2;
    if (base_ii >= cnt) return;

    float4 gv = *reinterpret_cast<const float4*>(gamma + lane*4);
    float4 bv = *reinterpret_cast<const float4*>(beta  + lane*4);

#pragma unroll
    for (int r = 0; r < 2; r++) {
        int ii = base_ii + r;
        if (ii >= cnt) continue;
        int g = b*NN + g_act[b*NN + ii];

        float4 a = make_float4(0.f,0.f,0.f,0.f);
        float tot = 0.f;
#pragma unroll
        for (int s = 0; s < SPLIT; s++) {
            const float4* pp = reinterpret_cast<const float4*>(
                g_pacc + (size_t)s*BB*NN*DD + ((size_t)b*NN + ii)*DD);
            float4 t = pp[lane];
            a.x += t.x; a.y += t.y; a.z += t.z; a.w += t.w;
            tot += g_psumP[s][b*NN + ii];
        }

        float inv;
        if (tot > 0.f) {
            inv = 1.f / tot;
        } else {
            // exact fallback: zero-neighbor row -> uniform softmax over all N
            a = make_float4(0.f,0.f,0.f,0.f);
            const unsigned short* hb = g_hcb + (size_t)b*NN*DD + lane*4;
            for (int jj = 0; jj < cnt; jj++) {
                uint2 hv = *reinterpret_cast<const uint2*>(hb + (size_t)jj*DD);
                float2 f0 = __bfloat1622float2(*reinterpret_cast<__nv_bfloat162*>(&hv.x));
                float2 f1 = __bfloat1622float2(*reinterpret_cast<__nv_bfloat162*>(&hv.y));
                a.x += f0.x; a.y += f0.y; a.z += f1.x; a.w += f1.y;
            }
            inv = 1.f / (float)NN;
        }

        float4 x4 = *reinterpret_cast<const float4*>(x + (size_t)g*DD + lane*4);
        float4 v;
        v.x = a.x*inv + x4.x;  v.y = a.y*inv + x4.y;
        v.z = a.z*inv + x4.z;  v.w = a.w*inv + x4.w;
        float s1 = v.x + v.y + v.z + v.w;
        float s2 = v.x*v.x + v.y*v.y + v.z*v.z + v.w*v.w;
#pragma unroll
        for (int off = 16; off; off >>= 1) {
            s1 += __shfl_xor_sync(0xffffffffu, s1, off);
            s2 += __shfl_xor_sync(0xffffffffu, s2, off);
        }
        float mu  = s1 * (1.f/128.f);
        float var = s2 * (1.f/128.f) - mu*mu;
        float rs  = rsqrtf(var + 1e-5f);
        float4 o;
        o.x = (v.x - mu)*rs*gv.x + bv.x;
        o.y = (v.y - mu)*rs*gv.y + bv.y;
        o.z = (v.z - mu)*rs*gv.z + bv.z;
        o.w = (v.w - mu)*rs*gv.w + bv.w;
        *reinterpret_cast<float4*>(out + (size_t)g*DD + lane*4) = o;
    }
}

// ---------------- launcher ---------------------------------------------------
extern "C" void kernel_launch(void* const* d_in, const int* in_sizes, int n_in,
                              void* d_out, int out_size) {
    const float* x     = (const float*)d_in[0];
    const int*   adj   = (const int*)  d_in[1];
    const int*   nm    = (const int*)  d_in[2];
    const float* W     = (const float*)d_in[3];
    const float* a_l   = (const float*)d_in[4];
    const float* a_r   = (const float*)d_in[5];
    const float* gamma = (const float*)d_in[6];
    const float* beta  = (const float*)d_in[7];
    float* out = (float*)d_out;

    k1_compact<<<BB, 256>>>(nm);
    k2_gemm<<<(BB*NN)/32, 128>>>(x, nm, W, a_l, a_r, beta, out);
    k3_adjc<<<dim3(NN/4, BB), 256>>>(adj);
    k4_attn<<<dim3(NN/64, SPLIT, BB), 256>>>();
    k5_finish<<<dim3(NN/8, BB), 128>>>(x, gamma, beta, out);
}

// round 7
// speedup vs baseline: 2.5653x; 1.1405x over previous
#include <cuda_runtime.h>
#include <cuda_bf16.h>
#include <cstdint>

#define BB 8
#define NN 2048
#define DD 128
#define LOG2E 1.44269504f
#define NW (NN/32)
#define SPLIT 2
#define PSTR 40      // P smem row stride (bf16 units)
#define HSTR 136     // H smem row stride (bf16 units)
#define PBUFB (64*PSTR*2)
#define HBUFB (32*HSTR*2)

// ---------------- device scratch ----------------
__device__ unsigned short g_hcb [BB*NN*DD];   // compacted h, bf16 (padded rows stay 0)
__device__ unsigned       g_eln [BB*NN];      // packed (bf16 exp(.2el) << 16) | bf16 exp(el)
__device__ unsigned short g_er1c[BB*NN];      // bf16 exp(er)      (padded stay 0)
__device__ unsigned short g_er2c[BB*NN];      // bf16 exp(.2 er)
__device__ int            g_act [BB*NN];
__device__ int            g_posm[BB*NN];      // node -> compacted pos (or -1)
__device__ int            g_cnt [BB];
__device__ unsigned       g_adjc[(size_t)BB*NN*NW];
__device__ float          g_pacc[(size_t)SPLIT*BB*NN*DD];
__device__ float          g_psumP[SPLIT][BB*NN];

// ---- helpers ----
__device__ __forceinline__ unsigned hmul2u(unsigned a, unsigned b) {
    __nv_bfloat162 r = __hmul2(*reinterpret_cast<__nv_bfloat162*>(&a),
                               *reinterpret_cast<__nv_bfloat162*>(&b));
    return *reinterpret_cast<unsigned*>(&r);
}
__device__ __forceinline__ unsigned hmax2u(unsigned a, unsigned b) {
    __nv_bfloat162 r = __hmax2(*reinterpret_cast<__nv_bfloat162*>(&a),
                               *reinterpret_cast<__nv_bfloat162*>(&b));
    return *reinterpret_cast<unsigned*>(&r);
}
__device__ __forceinline__ unsigned bpack(float x, float y) {
    __nv_bfloat162 r = __float22bfloat162_rn(make_float2(x, y));
    return *reinterpret_cast<unsigned*>(&r);
}
__device__ __forceinline__ void ldsm_x4(unsigned& r0, unsigned& r1,
                                        unsigned& r2, unsigned& r3, unsigned addr) {
    asm volatile("ldmatrix.sync.aligned.m8n8.x4.shared.b16 {%0,%1,%2,%3}, [%4];"
                 : "=r"(r0), "=r"(r1), "=r"(r2), "=r"(r3) : "r"(addr));
}
__device__ __forceinline__ void ldsm_x4_t(unsigned& r0, unsigned& r1,
                                          unsigned& r2, unsigned& r3, unsigned addr) {
    asm volatile("ldmatrix.sync.aligned.m8n8.x4.trans.shared.b16 {%0,%1,%2,%3}, [%4];"
                 : "=r"(r0), "=r"(r1), "=r"(r2), "=r"(r3) : "r"(addr));
}
__device__ __forceinline__ void mma_bf16(float4& d, unsigned a0, unsigned a1,
                                         unsigned a2, unsigned a3,
                                         unsigned b0, unsigned b1) {
    asm volatile("mma.sync.aligned.m16n8k16.row.col.f32.bf16.bf16.f32 "
        "{%0,%1,%2,%3}, {%4,%5,%6,%7}, {%8,%9}, {%0,%1,%2,%3};"
        : "+f"(d.x), "+f"(d.y), "+f"(d.z), "+f"(d.w)
        : "r"(a0), "r"(a1), "r"(a2), "r"(a3), "r"(b0), "r"(b1));
}
#define CP_ASYNC16(dst, src) \
    asm volatile("cp.async.cg.shared.global [%0], [%1], 16;" :: "r"(dst), "l"(src))
#define CP_COMMIT asm volatile("cp.async.commit_group;" ::: "memory")
#define CP_WAIT0  asm volatile("cp.async.wait_group 0;" ::: "memory")

// ---------------- K1: deterministic compaction ----------------
__global__ void k1_compact(const int* __restrict__ nm) {
    int b = blockIdx.x, t = threadIdx.x;
    __shared__ int part[256];
    const int* m = nm + b*NN;
    int base = t*8, flags[8], c = 0;
#pragma unroll
    for (int k = 0; k < 8; k++) { flags[k] = (m[base+k] != 0); c += flags[k]; }
    part[t] = c; __syncthreads();
    for (int off = 1; off < 256; off <<= 1) {
        int add = (t >= off) ? part[t-off] : 0;
        __syncthreads(); part[t] += add; __syncthreads();
    }
    int pos = part[t] - c;
#pragma unroll
    for (int k = 0; k < 8; k++) {
        if (flags[k]) { g_act[b*NN + pos] = base + k; g_posm[b*NN + base + k] = pos; pos++; }
        else g_posm[b*NN + base + k] = -1;
    }
    if (t == 255) g_cnt[b] = part[255];
}

// ---------------- K2: h = x_active @ W over compacted rows only -------------
__global__ __launch_bounds__(128) void k2_gemm(
    const float* __restrict__ x, const float* __restrict__ W,
    const float* __restrict__ a_l, const float* __restrict__ a_r)
{
    int b = blockIdx.y;
    int cnt = g_cnt[b];
    int c0 = blockIdx.x * 32;
    if (c0 >= cnt) return;

    __shared__ float xs[32][DD];
    int tid = threadIdx.x, tx = tid & 31, ty = tid >> 5;

#pragma unroll 4
    for (int i = 0; i < 32; i++) {
        int ii = c0 + i;
        int row = g_act[b*NN + ((ii < cnt) ? ii : (cnt - 1))];
        xs[i][tid] = x[((size_t)b*NN + row)*DD + tid];
    }
    __syncthreads();

    float4 acc[8];
#pragma unroll
    for (int r = 0; r < 8; r++) acc[r] = make_float4(0.f,0.f,0.f,0.f);

    const float4* W4 = reinterpret_cast<const float4*>(W);
#pragma unroll 4
    for (int k = 0; k < DD; k++) {
        float4 w4 = W4[k*32 + tx];
#pragma unroll
        for (int r = 0; r < 8; r++) {
            float xv = xs[ty*8 + r][k];
            acc[r].x += xv*w4.x; acc[r].y += xv*w4.y;
            acc[r].z += xv*w4.z; acc[r].w += xv*w4.w;
        }
    }

    float4 alv = *reinterpret_cast<const float4*>(a_l + tx*4);
    float4 arv = *reinterpret_cast<const float4*>(a_r + tx*4);
#pragma unroll
    for (int r = 0; r < 8; r++) {
        int ii = c0 + ty*8 + r;
        bool live = (ii < cnt);
        if (live) {
            uint2 hv = make_uint2(bpack(acc[r].x, acc[r].y), bpack(acc[r].z, acc[r].w));
            *reinterpret_cast<uint2*>(&g_hcb[(size_t)(b*NN + ii)*DD + tx*4]) = hv;
        }
        float pl = acc[r].x*alv.x + acc[r].y*alv.y + acc[r].z*alv.z + acc[r].w*alv.w;
        float pr = acc[r].x*arv.x + acc[r].y*arv.y + acc[r].z*arv.z + acc[r].w*arv.w;
#pragma unroll
        for (int off = 16; off; off >>= 1) {
            pl += __shfl_down_sync(0xffffffffu, pl, off);
            pr += __shfl_down_sync(0xffffffffu, pr, off);
        }
        if (tx == 0 && live) {
            g_eln[b*NN + ii] = bpack(exp2f(pl*LOG2E), exp2f(0.2f*pl*LOG2E));
            __nv_bfloat16 r1 = __float2bfloat16(exp2f(pr*LOG2E));
            __nv_bfloat16 r2 = __float2bfloat16(exp2f(0.2f*pr*LOG2E));
            g_er1c[b*NN + ii] = *reinterpret_cast<unsigned short*>(&r1);
            g_er2c[b*NN + ii] = *reinterpret_cast<unsigned short*>(&r2);
        }
    }
}

// ---------------- K2b: masked rows -> beta (out row==0 -> LN -> beta) -------
__global__ __launch_bounds__(256) void k2_beta(
    const float* __restrict__ beta, float* __restrict__ out)
{
    int g = blockIdx.x*2 + (threadIdx.x >> 7);
    int tid = threadIdx.x & 127;
    if (g_posm[g] < 0) out[(size_t)g*DD + tid] = beta[tid];
}

// ---------------- K3: coalesced adj row -> bitmask -> compacted bitmask -----
__global__ __launch_bounds__(256) void k3_adjc(const int* __restrict__ adj) {
    int b = blockIdx.y;
    int cnt = g_cnt[b];
    int ii = blockIdx.x;
    if (ii >= cnt) return;
    int pad = (cnt + 31) & ~31;
    int i = g_act[b*NN + ii];

    __shared__ unsigned ubits[64];
    int t = threadIdx.x, lane = t & 31, w = t >> 5;
    const int* arow = adj + ((size_t)b*NN + i)*NN;
#pragma unroll
    for (int q = 0; q < 8; q++) {
        int a = arow[q*256 + t];                       // fully coalesced 1KB/iter
        unsigned word = __ballot_sync(0xffffffffu, a != 0);
        if (lane == 0) ubits[q*8 + w] = word;
    }
    __syncthreads();

    const int* actb = g_act + b*NN;
    unsigned* dst = g_adjc + ((size_t)b*NN + ii)*NW;
    for (int jj = t; jj < pad; jj += 256) {
        unsigned bit = 0;
        if (jj < cnt) {
            int j = actb[jj];
            bit = (ubits[j >> 5] >> (j & 31)) & 1u;
        }
        unsigned word = __ballot_sync(0xffffffffu, bit);
        if (lane == 0) dst[jj >> 5] = word;
    }
}

// ---------------- K4: exp-free bf16 tensor P@H + tensor psum ----------------
__device__ __forceinline__ unsigned pmix(unsigned El1, unsigned El2,
                                         unsigned e1, unsigned e2, unsigned m) {
    return hmax2u(hmul2u(El1, e1), hmul2u(El2, e2)) & m;
}

__global__ __launch_bounds__(256,3) void k4_attn(void)
{
    __shared__ __align__(16) unsigned short Pp[2][64][PSTR];
    __shared__ __align__(16) unsigned short Hs[2][32][HSTR];
    __shared__ unsigned lutm[4];

    int b = blockIdx.z, sid = blockIdx.y;
    int cnt = g_cnt[b];
    int base = blockIdx.x * 64;
    if (base >= cnt) return;

    int tid = threadIdx.x, lane = tid & 31, wid = tid >> 5;
    int mw = wid >> 2, nw = wid & 3, wd = nw*32;
    if (tid < 4) lutm[tid] = ((tid & 1) ? 0xFFFFu : 0u) | ((tid & 2) ? 0xFFFF0000u : 0u);

    int nch = (cnt + 31) >> 5;
    int cs  = (nch + SPLIT - 1) / SPLIT;
    int jc0 = sid * cs;
    int jc1 = min(nch, jc0 + cs);

    int prow = tid >> 2, jq = (tid & 3) * 8;
    int iw = min(base + prow, cnt - 1);
    unsigned eln = g_eln[b*NN + iw];
    unsigned El1 = __byte_perm(eln, eln, 0x1010);
    unsigned El2 = __byte_perm(eln, eln, 0x3232);
    const unsigned* adjp = g_adjc + ((size_t)b*NN + iw)*NW;
    const unsigned short* er1b = g_er1c + b*NN;
    const unsigned short* er2b = g_er2c + b*NN;

    int hrow = tid >> 3, hseg = (tid & 7) * 16;
    const unsigned short* hsrc0 = g_hcb + (size_t)b*NN*DD;

    float4 acc[2][4]; float4 ps[2];
#pragma unroll
    for (int mt = 0; mt < 2; mt++) {
        ps[mt] = make_float4(0.f,0.f,0.f,0.f);
#pragma unroll
        for (int nt = 0; nt < 4; nt++) acc[mt][nt] = make_float4(0.f,0.f,0.f,0.f);
    }

    unsigned Pbase = (unsigned)__cvta_generic_to_shared(&Pp[0][0][0]);
    unsigned Hbase = (unsigned)__cvta_generic_to_shared(&Hs[0][0][0]);
    unsigned aaddr = Pbase + (unsigned)((mw*32 + (lane & 15))*PSTR*2 + ((lane >> 4) & 1)*16);
    unsigned baddr = Hbase + (unsigned)(((((lane >> 3) & 1)*8) + (lane & 7))*HSTR*2
                                        + (wd + ((lane >> 4) & 1)*8)*2);
    unsigned pdst = Pbase + (unsigned)(prow*PSTR*2 + jq*2);
    unsigned hdst = Hbase + (unsigned)(hrow*HSTR*2 + hseg*2);
    const unsigned ONES = 0x3F803F80u;

    __syncthreads();

    if (jc0 < jc1) {
        unsigned w = adjp[jc0] >> jq;
        uint4 e1 = *reinterpret_cast<const uint4*>(er1b + jc0*32 + jq);
        uint4 e2 = *reinterpret_cast<const uint4*>(er2b + jc0*32 + jq);
        uint4 o;
        o.x = pmix(El1, El2, e1.x, e2.x, lutm[w & 3]);
        o.y = pmix(El1, El2, e1.y, e2.y, lutm[(w >> 2) & 3]);
        o.z = pmix(El1, El2, e1.z, e2.z, lutm[(w >> 4) & 3]);
        o.w = pmix(El1, El2, e1.w, e2.w, lutm[(w >> 6) & 3]);
        asm volatile("st.shared.v4.b32 [%0], {%1,%2,%3,%4};"
                     :: "r"(pdst), "r"(o.x), "r"(o.y), "r"(o.z), "r"(o.w));
        const unsigned short* src = hsrc0 + ((size_t)(jc0*32 + hrow))*DD + hseg;
        CP_ASYNC16(hdst, src);
        CP_ASYNC16(hdst + 16, src + 8);
        CP_COMMIT;
    }

    for (int jc = jc0; jc < jc1; jc++) {
        int cur = (jc - jc0) & 1, nxt = cur ^ 1;
        CP_WAIT0;
        __syncthreads();

        if (jc + 1 < jc1) {
            unsigned w = adjp[jc+1] >> jq;
            uint4 e1 = *reinterpret_cast<const uint4*>(er1b + (jc+1)*32 + jq);
            uint4 e2 = *reinterpret_cast<const uint4*>(er2b + (jc+1)*32 + jq);
            uint4 o;
            o.x = pmix(El1, El2, e1.x, e2.x, lutm[w & 3]);
            o.y = pmix(El1, El2, e1.y, e2.y, lutm[(w >> 2) & 3]);
            o.z = pmix(El1, El2, e1.z, e2.z, lutm[(w >> 4) & 3]);
            o.w = pmix(El1, El2, e1.w, e2.w, lutm[(w >> 6) & 3]);
            asm volatile("st.shared.v4.b32 [%0], {%1,%2,%3,%4};"
                         :: "r"(pdst + nxt*PBUFB), "r"(o.x), "r"(o.y), "r"(o.z), "r"(o.w));
            const unsigned short* src = hsrc0 + ((size_t)((jc+1)*32 + hrow))*DD + hseg;
            CP_ASYNC16(hdst + nxt*HBUFB, src);
            CP_ASYNC16(hdst + nxt*HBUFB + 16, src + 8);
            CP_COMMIT;
        }

        unsigned pa = aaddr + cur*PBUFB;
        unsigned hb = baddr + cur*HBUFB;
#pragma unroll
        for (int ks = 0; ks < 2; ks++) {
            unsigned bf[8];
            ldsm_x4_t(bf[0], bf[1], bf[2], bf[3], hb + ks*16*HSTR*2);
            ldsm_x4_t(bf[4], bf[5], bf[6], bf[7], hb + ks*16*HSTR*2 + 32);
            unsigned a0[4], a1[4];
            ldsm_x4(a0[0], a0[1], a0[2], a0[3], pa + ks*32);
            ldsm_x4(a1[0], a1[1], a1[2], a1[3], pa + 16*PSTR*2 + ks*32);
#pragma unroll
            for (int nt = 0; nt < 4; nt++) {
                mma_bf16(acc[0][nt], a0[0],a0[1],a0[2],a0[3], bf[nt*2], bf[nt*2+1]);
                mma_bf16(acc[1][nt], a1[0],a1[1],a1[2],a1[3], bf[nt*2], bf[nt*2+1]);
            }
            if (nw == 0) {
                mma_bf16(ps[0], a0[0],a0[1],a0[2],a0[3], ONES, ONES);
                mma_bf16(ps[1], a1[0],a1[1],a1[2],a1[3], ONES, ONES);
            }
        }
    }

    int gid = lane >> 2, tig = lane & 3;
    if (nw == 0 && tig == 0) {
#pragma unroll
        for (int mt = 0; mt < 2; mt++) {
            int i0 = base + mw*32 + mt*16 + gid;
            g_psumP[sid][b*NN + i0]     = ps[mt].x;
            g_psumP[sid][b*NN + i0 + 8] = ps[mt].z;
        }
    }

    float* pb = g_pacc + (size_t)sid*BB*NN*DD + (size_t)b*NN*DD;
#pragma unroll
    for (int mt = 0; mt < 2; mt++) {
        int i0 = base + mw*32 + mt*16 + gid;
#pragma unroll
        for (int nt = 0; nt < 4; nt++) {
            int d0 = wd + nt*8 + 2*tig;
            *reinterpret_cast<float2*>(&pb[(size_t)i0*DD + d0]) =
                make_float2(acc[mt][nt].x, acc[mt][nt].y);
            *reinterpret_cast<float2*>(&pb[(size_t)(i0+8)*DD + d0]) =
                make_float2(acc[mt][nt].z, acc[mt][nt].w);
        }
    }
}

// ---------------- K5: reduce splits + normalize + residual + LayerNorm ------
__global__ __launch_bounds__(128) void k5_finish(
    const float* __restrict__ x, const float* __restrict__ gamma,
    const float* __restrict__ beta, float* __restrict__ out)
{
    int b = blockIdx.y;
    int cnt = g_cnt[b];
    int lane = threadIdx.x & 31, wid = threadIdx.x >> 5;
    int base_ii = blockIdx.x * 8 + wid * 2;
    if (base_ii >= cnt) return;

    float4 gv = *reinterpret_cast<const float4*>(gamma + lane*4);
    float4 bv = *reinterpret_cast<const float4*>(beta  + lane*4);

#pragma unroll
    for (int r = 0; r < 2; r++) {
        int ii = base_ii + r;
        if (ii >= cnt) continue;
        int g = b*NN + g_act[b*NN + ii];

        float4 a = make_float4(0.f,0.f,0.f,0.f);
        float tot = 0.f;
#pragma unroll
        for (int s = 0; s < SPLIT; s++) {
            const float4* pp = reinterpret_cast<const float4*>(
                g_pacc + (size_t)s*BB*NN*DD + ((size_t)b*NN + ii)*DD);
            float4 t = pp[lane];
            a.x += t.x; a.y += t.y; a.z += t.z; a.w += t.w;
            tot += g_psumP[s][b*NN + ii];
        }

        float inv;
        if (tot > 0.f) {
            inv = 1.f / tot;
        } else {
            a = make_float4(0.f,0.f,0.f,0.f);
            const unsigned short* hb = g_hcb + (size_t)b*NN*DD + lane*4;
            for (int jj = 0; jj < cnt; jj++) {
                uint2 hv = *reinterpret_cast<const uint2*>(hb + (size_t)jj*DD);
                float2 f0 = __bfloat1622float2(*reinterpret_cast<__nv_bfloat162*>(&hv.x));
                float2 f1 = __bfloat1622float2(*reinterpret_cast<__nv_bfloat162*>(&hv.y));
                a.x += f0.x; a.y += f0.y; a.z += f1.x; a.w += f1.y;
            }
            inv = 1.f / (float)NN;
        }

        float4 x4 = *reinterpret_cast<const float4*>(x + (size_t)g*DD + lane*4);
        float4 v;
        v.x = a.x*inv + x4.x;  v.y = a.y*inv + x4.y;
        v.z = a.z*inv + x4.z;  v.w = a.w*inv + x4.w;
        float s1 = v.x + v.y + v.z + v.w;
        float s2 = v.x*v.x + v.y*v.y + v.z*v.z + v.w*v.w;
#pragma unroll
        for (int off = 16; off; off >>= 1) {
            s1 += __shfl_xor_sync(0xffffffffu, s1, off);
            s2 += __shfl_xor_sync(0xffffffffu, s2, off);
        }
        float mu  = s1 * (1.f/128.f);
        float var = s2 * (1.f/128.f) - mu*mu;
        float rs  = rsqrtf(var + 1e-5f);
        float4 o;
        o.x = (v.x - mu)*rs*gv.x + bv.x;
        o.y = (v.y - mu)*rs*gv.y + bv.y;
        o.z = (v.z - mu)*rs*gv.z + bv.z;
        o.w = (v.w - mu)*rs*gv.w + bv.w;
        *reinterpret_cast<float4*>(out + (size_t)g*DD + lane*4) = o;
    }
}

// ---------------- launcher ---------------------------------------------------
extern "C" void kernel_launch(void* const* d_in, const int* in_sizes, int n_in,
                              void* d_out, int out_size) {
    const float* x     = (const float*)d_in[0];
    const int*   adj   = (const int*)  d_in[1];
    const int*   nm    = (const int*)  d_in[2];
    const float* W     = (const float*)d_in[3];
    const float* a_l   = (const float*)d_in[4];
    const float* a_r   = (const float*)d_in[5];
    const float* gamma = (const float*)d_in[6];
    const float* beta  = (const float*)d_in[7];
    float* out = (float*)d_out;

    k1_compact<<<BB, 256>>>(nm);
    k2_gemm<<<dim3(NN/32, BB), 128>>>(x, W, a_l, a_r);
    k2_beta<<<(BB*NN)/2, 256>>>(beta, out);
    k3_adjc<<<dim3(NN, BB), 256>>>(adj);
    k4_attn<<<dim3(NN/64, SPLIT, BB), 256>>>();
    k5_finish<<<dim3(NN/8, BB), 128>>>(x, gamma, beta, out);
}